// round 9
// baseline (speedup 1.0000x reference)
#include <cuda_runtime.h>
#include <math.h>

#define BB 4
#define SS 2048
#define DD 512
#define HH 8
#define HD 64
#define BH (BB*HH)

__device__ float    g_q[BH * SS * HD];
__device__ float    g_k[BH * SS * HD];
__device__ float    g_v[BH * SS * HD];
__device__ float    g_x[BB * SS * DD];
__device__ unsigned g_mbits[BB * SS * (SS/32)];

// ---------------------------------------------------------------------------
__device__ __forceinline__ unsigned f2tf(float x) {
    unsigned r;
    asm("cvt.rna.tf32.f32 %0, %1;" : "=r"(r) : "f"(x));
    return r;
}
__device__ __forceinline__ void mma_tf32(float c[4], const unsigned a[4], const unsigned b[2]) {
    asm volatile(
        "mma.sync.aligned.m16n8k8.row.col.f32.tf32.tf32.f32 "
        "{%0,%1,%2,%3},{%4,%5,%6,%7},{%8,%9},{%0,%1,%2,%3};"
        : "+f"(c[0]), "+f"(c[1]), "+f"(c[2]), "+f"(c[3])
        : "r"(a[0]), "r"(a[1]), "r"(a[2]), "r"(a[3]), "r"(b[0]), "r"(b[1]));
}

// ---------------------------------------------------------------------------
__global__ __launch_bounds__(256) void pack_mask_kernel(
    const int* __restrict__ mask, unsigned* __restrict__ bits)
{
    int w = blockIdx.x * 256 + threadIdx.x;
    const int4* p = (const int4*)(mask + (size_t)w * 32);
    unsigned v = 0;
    #pragma unroll
    for (int i = 0; i < 8; i++) {
        int4 q = p[i];
        v |= (unsigned)(q.x != 0) << (i * 4 + 0);
        v |= (unsigned)(q.y != 0) << (i * 4 + 1);
        v |= (unsigned)(q.z != 0) << (i * 4 + 2);
        v |= (unsigned)(q.w != 0) << (i * 4 + 3);
    }
    bits[w] = v;
}

// ---------------------------------------------------------------------------
// Projection GEMM body (R3-proven): C = X @ W^T + bias.
// Block 128x128, 256 thr, 8 warps (2m x 4n, warp 64x32), k-tile 32.
// ---------------------------------------------------------------------------
__device__ __forceinline__ void proj_body(
    const float* __restrict__ X, const float* __restrict__ W,
    const float* __restrict__ bias, float* __restrict__ out, int scatter,
    int m0, int n0)
{
    __shared__ __align__(16) unsigned As[128 * 36];
    __shared__ __align__(16) unsigned Bs[128 * 36];

    const int t = threadIdx.x;
    const int warp = t >> 5, lane = t & 31;
    const int wm = warp >> 2, wn = warp & 3;
    const int g = lane >> 2, tig = lane & 3;

    float acc[4][4][4] = {};

    for (int k0 = 0; k0 < DD; k0 += 32) {
        #pragma unroll
        for (int i = 0; i < 4; i++) {
            int f = i * 256 + t;
            int r = f >> 3, c4 = (f & 7) * 4;
            float4 xv = *(const float4*)&X[(size_t)(m0 + r) * DD + k0 + c4];
            *(uint4*)&As[r * 36 + c4] = make_uint4(f2tf(xv.x), f2tf(xv.y), f2tf(xv.z), f2tf(xv.w));
            float4 wv = *(const float4*)&W[(size_t)(n0 + r) * DD + k0 + c4];
            *(uint4*)&Bs[r * 36 + c4] = make_uint4(f2tf(wv.x), f2tf(wv.y), f2tf(wv.z), f2tf(wv.w));
        }
        __syncthreads();

        #pragma unroll
        for (int kk = 0; kk < 32; kk += 8) {
            unsigned af[4][4], bf[4][2];
            #pragma unroll
            for (int mt = 0; mt < 4; mt++) {
                int mrow = wm * 64 + mt * 16;
                af[mt][0] = As[(mrow + g) * 36 + kk + tig];
                af[mt][1] = As[(mrow + g + 8) * 36 + kk + tig];
                af[mt][2] = As[(mrow + g) * 36 + kk + tig + 4];
                af[mt][3] = As[(mrow + g + 8) * 36 + kk + tig + 4];
            }
            #pragma unroll
            for (int nt = 0; nt < 4; nt++) {
                int ncol = wn * 32 + nt * 8 + g;
                bf[nt][0] = Bs[ncol * 36 + kk + tig];
                bf[nt][1] = Bs[ncol * 36 + kk + tig + 4];
            }
            #pragma unroll
            for (int mt = 0; mt < 4; mt++)
                #pragma unroll
                for (int nt = 0; nt < 4; nt++)
                    mma_tf32(acc[mt][nt], af[mt], bf[nt]);
        }
        __syncthreads();
    }

    #pragma unroll
    for (int nt = 0; nt < 4; nt++) {
        const int col = n0 + wn * 32 + nt * 8 + 2 * tig;
        const float b0v = bias[col], b1v = bias[col + 1];
        #pragma unroll
        for (int mt = 0; mt < 4; mt++) {
            #pragma unroll
            for (int half = 0; half < 2; half++) {
                int m = m0 + wm * 64 + mt * 16 + g + half * 8;
                float2 v;
                v.x = acc[mt][nt][half * 2 + 0] + b0v;
                v.y = acc[mt][nt][half * 2 + 1] + b1v;
                if (scatter) {
                    int b = m >> 11, s = m & (SS - 1);
                    int h = col >> 6, hd = col & (HD - 1);
                    *(float2*)&out[(((size_t)(b * HH + h)) * SS + s) * HD + hd] = v;
                } else {
                    *(float2*)&out[(size_t)m * DD + col] = v;
                }
            }
        }
    }
}

// Fused QKV projections: gridDim.z selects which projection.
__global__ __launch_bounds__(256) void qkv_proj(
    const float* __restrict__ Q, const float* __restrict__ K, const float* __restrict__ V,
    const float* __restrict__ Wq, const float* __restrict__ bq,
    const float* __restrict__ Wk, const float* __restrict__ bk,
    const float* __restrict__ Wv, const float* __restrict__ bv,
    float* __restrict__ oq, float* __restrict__ ok, float* __restrict__ ov)
{
    const float *X, *W, *bias; float* out;
    if (blockIdx.z == 0)      { X = Q; W = Wq; bias = bq; out = oq; }
    else if (blockIdx.z == 1) { X = K; W = Wk; bias = bk; out = ok; }
    else                      { X = V; W = Wv; bias = bv; out = ov; }
    proj_body(X, W, bias, out, 1, blockIdx.y * 128, blockIdx.x * 128);
}

__global__ __launch_bounds__(256) void proj_mma(
    const float* __restrict__ X, const float* __restrict__ W,
    const float* __restrict__ bias, float* __restrict__ out, int scatter)
{
    proj_body(X, W, bias, out, scatter, blockIdx.y * 128, blockIdx.x * 128);
}

// ---------------------------------------------------------------------------
// Single-pass fused attention. Block owns (bh, 128 q-rows), 256 threads.
// Per n-tile: scores MMA -> exp/mask -> write UNNORMALIZED dist, tf32 P,
// rowsum accumulate -> PV MMA (unnormalized). End: scale y by 1/rowsum,
// write x, then normalize own dist rows in place (L2-hot).
// smem words: Qs[128*68] | Ks[128*68] | Vs[128*72] | Ps[128*132] | rowsum[128]
// ---------------------------------------------------------------------------
#define QS_OFF   0
#define KS_OFF   8704
#define VS_OFF   17408
#define PS_OFF   26624
#define RS_OFF   43520
#define ATTN_SMEM_W 43648   // 174,592 B

__global__ __launch_bounds__(256) void attn_fused(float* __restrict__ dist)
{
    extern __shared__ unsigned sm[];
    unsigned* Qs = sm + QS_OFF;
    unsigned* Ks = sm + KS_OFF;
    unsigned* Vs = sm + VS_OFF;
    unsigned* Ps = sm + PS_OFF;
    float* rowsum = (float*)(sm + RS_OFF);

    const int t = threadIdx.x;
    const int warp = t >> 5, lane = t & 31;
    const int wm = warp >> 2, wn = warp & 3;       // scores: 2m x 4n (warp 64x32)
    const int wm2 = warp >> 1, wn2 = warp & 1;     // PV:     4m x 2n (warp 32x32)
    const int g = lane >> 2, tig = lane & 3;
    const int bh = blockIdx.y, b = bh >> 3, h = bh & 7;
    const int m0 = blockIdx.x * 128;

    const float* q = g_q + (size_t)bh * SS * HD;
    const float* k = g_k + (size_t)bh * SS * HD;
    const float* v = g_v + (size_t)bh * SS * HD;

    // load Q tile (resident, tf32)
    #pragma unroll
    for (int i = 0; i < 8; i++) {
        int f = i * 256 + t;
        int r = f >> 4, c4 = (f & 15) * 4;
        float4 qv = *(const float4*)&q[(size_t)(m0 + r) * HD + c4];
        *(uint4*)&Qs[r * 68 + c4] = make_uint4(f2tf(qv.x), f2tf(qv.y), f2tf(qv.z), f2tf(qv.w));
    }
    if (t < 128) rowsum[t] = 0.0f;

    float rs[4][2] = {};
    float y[2][4][4] = {};
    const size_t dbase = (size_t)bh * SS * SS;

    for (int it = 0; it < 16; it++) {
        const int n0 = it * 128;
        __syncthreads();   // prev iter's K/V reads complete (and Q/rowsum on it==0)
        #pragma unroll
        for (int i = 0; i < 8; i++) {
            int f = i * 256 + t;
            int r = f >> 4, c4 = (f & 15) * 4;
            float4 kv = *(const float4*)&k[(size_t)(n0 + r) * HD + c4];
            *(uint4*)&Ks[r * 68 + c4] = make_uint4(f2tf(kv.x), f2tf(kv.y), f2tf(kv.z), f2tf(kv.w));
            float4 vv = *(const float4*)&v[(size_t)(n0 + r) * HD + c4];
            *(uint4*)&Vs[r * 72 + c4] = make_uint4(f2tf(vv.x), f2tf(vv.y), f2tf(vv.z), f2tf(vv.w));
        }
        __syncthreads();

        // scores MMA: S = Q[128x64] . K^T[64x128]
        float acc[4][4][4] = {};
        #pragma unroll
        for (int kk = 0; kk < 64; kk += 8) {
            unsigned af[4][4], bf[4][2];
            #pragma unroll
            for (int mt = 0; mt < 4; mt++) {
                int mrow = wm * 64 + mt * 16;
                af[mt][0] = Qs[(mrow + g) * 68 + kk + tig];
                af[mt][1] = Qs[(mrow + g + 8) * 68 + kk + tig];
                af[mt][2] = Qs[(mrow + g) * 68 + kk + tig + 4];
                af[mt][3] = Qs[(mrow + g + 8) * 68 + kk + tig + 4];
            }
            #pragma unroll
            for (int nt = 0; nt < 4; nt++) {
                int ncol = wn * 32 + nt * 8 + g;
                bf[nt][0] = Ks[ncol * 68 + kk + tig];
                bf[nt][1] = Ks[ncol * 68 + kk + tig + 4];
            }
            #pragma unroll
            for (int mt = 0; mt < 4; mt++)
                #pragma unroll
                for (int nt = 0; nt < 4; nt++)
                    mma_tf32(acc[mt][nt], af[mt], bf[nt]);
        }

        // epilogue: exp/mask, write UNNORMALIZED dist, deposit tf32 P, rowsums
        #pragma unroll
        for (int mt = 0; mt < 4; mt++) {
            #pragma unroll
            for (int half = 0; half < 2; half++) {
                int rowl = wm * 64 + mt * 16 + g + half * 8;
                int row = m0 + rowl;
                unsigned mb = g_mbits[((size_t)b * SS + row) * (SS/32) + (n0 >> 5) + wn];
                #pragma unroll
                for (int nt = 0; nt < 4; nt++) {
                    int nloc = nt * 8 + 2 * tig;
                    float e0 = ((mb >> nloc) & 1u) ? 0.0f : __expf(acc[mt][nt][half*2+0] * 0.125f);
                    float e1 = ((mb >> (nloc+1)) & 1u) ? 0.0f : __expf(acc[mt][nt][half*2+1] * 0.125f);
                    rs[mt][half] += e0 + e1;
                    float2 ev; ev.x = e0; ev.y = e1;
                    *(float2*)&dist[dbase + (size_t)row * SS + n0 + wn * 32 + nloc] = ev;
                    uint2 pv; pv.x = f2tf(e0); pv.y = f2tf(e1);
                    *(uint2*)&Ps[rowl * 132 + wn * 32 + nloc] = pv;
                }
            }
        }
        __syncthreads();   // Ps visible

        // PV: y += P[128x128] @ V[128x64]; warp tile 32x32
        #pragma unroll
        for (int kk = 0; kk < 128; kk += 8) {
            unsigned af[2][4], bf[4][2];
            #pragma unroll
            for (int mt = 0; mt < 2; mt++) {
                int mrow = wm2 * 32 + mt * 16;
                af[mt][0] = Ps[(mrow + g) * 132 + kk + tig];
                af[mt][1] = Ps[(mrow + g + 8) * 132 + kk + tig];
                af[mt][2] = Ps[(mrow + g) * 132 + kk + tig + 4];
                af[mt][3] = Ps[(mrow + g + 8) * 132 + kk + tig + 4];
            }
            #pragma unroll
            for (int nt = 0; nt < 4; nt++) {
                int ncol = wn2 * 32 + nt * 8 + g;
                bf[nt][0] = Vs[(kk + tig) * 72 + ncol];
                bf[nt][1] = Vs[(kk + tig + 4) * 72 + ncol];
            }
            #pragma unroll
            for (int mt = 0; mt < 2; mt++)
                #pragma unroll
                for (int nt = 0; nt < 4; nt++)
                    mma_tf32(y[mt][nt], af[mt], bf[nt]);
        }
    }

    // reduce row sums (quad shuffle + shared atomics across 4 n-warps)
    #pragma unroll
    for (int mt = 0; mt < 4; mt++)
        #pragma unroll
        for (int half = 0; half < 2; half++) {
            float s = rs[mt][half];
            s += __shfl_xor_sync(0xffffffffu, s, 1);
            s += __shfl_xor_sync(0xffffffffu, s, 2);
            if (tig == 0)
                atomicAdd(&rowsum[wm * 64 + mt * 16 + g + half * 8], s);
        }
    __syncthreads();
    if (t < 128) rowsum[t] = 1.0f / rowsum[t];
    __syncthreads();

    // write x = y * inv(rowsum)
    #pragma unroll
    for (int mt = 0; mt < 2; mt++) {
        #pragma unroll
        for (int nt = 0; nt < 4; nt++) {
            #pragma unroll
            for (int half = 0; half < 2; half++) {
                int rowl = wm2 * 32 + mt * 16 + g + half * 8;
                int row = m0 + rowl;
                int col = wn2 * 32 + nt * 8 + 2 * tig;
                float inv = rowsum[rowl];
                float2 o;
                o.x = y[mt][nt][half * 2 + 0] * inv;
                o.y = y[mt][nt][half * 2 + 1] * inv;
                *(float2*)&g_x[((size_t)(b * SS + row)) * DD + h * HD + col] = o;
            }
        }
    }

    // normalize this block's dist rows in place (mostly L2-resident)
    for (int i = 0; i < 256; i++) {
        int id = i * 256 + t;              // 0 .. 65535
        int row = id >> 9;                 // 512 float4 per row
        int c4 = id & 511;
        float inv = rowsum[row];
        float4* p = (float4*)&dist[dbase + (size_t)(m0 + row) * SS] + c4;
        float4 d = *p;
        d.x *= inv; d.y *= inv; d.z *= inv; d.w *= inv;
        *p = d;
    }
}

// ---------------------------------------------------------------------------
extern "C" void kernel_launch(void* const* d_in, const int* in_sizes, int n_in,
                              void* d_out, int out_size)
{
    const float* Q  = (const float*)d_in[0];
    const float* K  = (const float*)d_in[1];
    const float* V  = (const float*)d_in[2];
    const int*   mask = (const int*)d_in[3];
    const float* Wq = (const float*)d_in[4];
    const float* bq = (const float*)d_in[5];
    const float* Wk = (const float*)d_in[6];
    const float* bk = (const float*)d_in[7];
    const float* Wv = (const float*)d_in[8];
    const float* bv = (const float*)d_in[9];
    const float* Wo = (const float*)d_in[10];
    const float* bo = (const float*)d_in[11];

    float* out_x    = (float*)d_out;
    float* out_dist = (float*)d_out + (size_t)BB * SS * DD;

    void* pq; void* pk; void* pv; void* px; void* pbits;
    cudaGetSymbolAddress(&pq, g_q);
    cudaGetSymbolAddress(&pk, g_k);
    cudaGetSymbolAddress(&pv, g_v);
    cudaGetSymbolAddress(&px, g_x);
    cudaGetSymbolAddress(&pbits, g_mbits);

    const int ATTN_SMEM = ATTN_SMEM_W * 4;     // 174,592 B
    cudaFuncSetAttribute(attn_fused, cudaFuncAttributeMaxDynamicSharedMemorySize, ATTN_SMEM);

    pack_mask_kernel<<<(BB * SS * (SS/32)) / 256, 256>>>(mask, (unsigned*)pbits);

    dim3 gqkv(DD / 128, (BB * SS) / 128, 3);                // (4, 64, 3)
    qkv_proj<<<gqkv, 256>>>(Q, K, V, Wq, bq, Wk, bk, Wv, bv,
                            (float*)pq, (float*)pk, (float*)pv);

    dim3 gattn(SS / 128, BH);                               // (16, 32)
    attn_fused<<<gattn, 256, ATTN_SMEM>>>(out_dist);

    dim3 gproj(DD / 128, (BB * SS) / 128);                  // (4, 64)
    proj_mma<<<gproj, 256>>>((const float*)px, Wo, bo, out_x, 0);
}

// round 10
// speedup vs baseline: 1.3472x; 1.3472x over previous
#include <cuda_runtime.h>
#include <math.h>

#define BB 4
#define SS 2048
#define DD 512
#define HH 8
#define HD 64
#define BH (BB*HH)

__device__ float    g_q[BH * SS * HD];
__device__ float    g_k[BH * SS * HD];
__device__ float    g_v[BH * SS * HD];
__device__ float    g_x[BB * SS * DD];
__device__ unsigned g_mbits[BB * SS * (SS/32)];

// ---------------------------------------------------------------------------
__device__ __forceinline__ unsigned f2tf(float x) {
    unsigned r;
    asm("cvt.rna.tf32.f32 %0, %1;" : "=r"(r) : "f"(x));
    return r;
}
__device__ __forceinline__ void mma_tf32(float c[4], const unsigned a[4], const unsigned b[2]) {
    asm volatile(
        "mma.sync.aligned.m16n8k8.row.col.f32.tf32.tf32.f32 "
        "{%0,%1,%2,%3},{%4,%5,%6,%7},{%8,%9},{%0,%1,%2,%3};"
        : "+f"(c[0]), "+f"(c[1]), "+f"(c[2]), "+f"(c[3])
        : "r"(a[0]), "r"(a[1]), "r"(a[2]), "r"(a[3]), "r"(b[0]), "r"(b[1]));
}

// ---------------------------------------------------------------------------
__global__ __launch_bounds__(256) void pack_mask_kernel(
    const int* __restrict__ mask, unsigned* __restrict__ bits)
{
    int w = blockIdx.x * 256 + threadIdx.x;
    const int4* p = (const int4*)(mask + (size_t)w * 32);
    unsigned v = 0;
    #pragma unroll
    for (int i = 0; i < 8; i++) {
        int4 q = p[i];
        v |= (unsigned)(q.x != 0) << (i * 4 + 0);
        v |= (unsigned)(q.y != 0) << (i * 4 + 1);
        v |= (unsigned)(q.z != 0) << (i * 4 + 2);
        v |= (unsigned)(q.w != 0) << (i * 4 + 3);
    }
    bits[w] = v;
}

// ---------------------------------------------------------------------------
// Projection GEMM body (R3-proven): C = X @ W^T + bias.
// Block 128x128, 256 thr, 8 warps (2m x 4n, warp 64x32), k-tile 32.
// ---------------------------------------------------------------------------
__device__ __forceinline__ void proj_body(
    const float* __restrict__ X, const float* __restrict__ W,
    const float* __restrict__ bias, float* __restrict__ out, int scatter,
    int m0, int n0)
{
    __shared__ __align__(16) unsigned As[128 * 36];
    __shared__ __align__(16) unsigned Bs[128 * 36];

    const int t = threadIdx.x;
    const int warp = t >> 5, lane = t & 31;
    const int wm = warp >> 2, wn = warp & 3;
    const int g = lane >> 2, tig = lane & 3;

    float acc[4][4][4] = {};

    for (int k0 = 0; k0 < DD; k0 += 32) {
        #pragma unroll
        for (int i = 0; i < 4; i++) {
            int f = i * 256 + t;
            int r = f >> 3, c4 = (f & 7) * 4;
            float4 xv = *(const float4*)&X[(size_t)(m0 + r) * DD + k0 + c4];
            *(uint4*)&As[r * 36 + c4] = make_uint4(f2tf(xv.x), f2tf(xv.y), f2tf(xv.z), f2tf(xv.w));
            float4 wv = *(const float4*)&W[(size_t)(n0 + r) * DD + k0 + c4];
            *(uint4*)&Bs[r * 36 + c4] = make_uint4(f2tf(wv.x), f2tf(wv.y), f2tf(wv.z), f2tf(wv.w));
        }
        __syncthreads();

        #pragma unroll
        for (int kk = 0; kk < 32; kk += 8) {
            unsigned af[4][4], bf[4][2];
            #pragma unroll
            for (int mt = 0; mt < 4; mt++) {
                int mrow = wm * 64 + mt * 16;
                af[mt][0] = As[(mrow + g) * 36 + kk + tig];
                af[mt][1] = As[(mrow + g + 8) * 36 + kk + tig];
                af[mt][2] = As[(mrow + g) * 36 + kk + tig + 4];
                af[mt][3] = As[(mrow + g + 8) * 36 + kk + tig + 4];
            }
            #pragma unroll
            for (int nt = 0; nt < 4; nt++) {
                int ncol = wn * 32 + nt * 8 + g;
                bf[nt][0] = Bs[ncol * 36 + kk + tig];
                bf[nt][1] = Bs[ncol * 36 + kk + tig + 4];
            }
            #pragma unroll
            for (int mt = 0; mt < 4; mt++)
                #pragma unroll
                for (int nt = 0; nt < 4; nt++)
                    mma_tf32(acc[mt][nt], af[mt], bf[nt]);
        }
        __syncthreads();
    }

    #pragma unroll
    for (int nt = 0; nt < 4; nt++) {
        const int col = n0 + wn * 32 + nt * 8 + 2 * tig;
        const float b0v = bias[col], b1v = bias[col + 1];
        #pragma unroll
        for (int mt = 0; mt < 4; mt++) {
            #pragma unroll
            for (int half = 0; half < 2; half++) {
                int m = m0 + wm * 64 + mt * 16 + g + half * 8;
                float2 v;
                v.x = acc[mt][nt][half * 2 + 0] + b0v;
                v.y = acc[mt][nt][half * 2 + 1] + b1v;
                if (scatter) {
                    int b = m >> 11, s = m & (SS - 1);
                    int h = col >> 6, hd = col & (HD - 1);
                    *(float2*)&out[(((size_t)(b * HH + h)) * SS + s) * HD + hd] = v;
                } else {
                    *(float2*)&out[(size_t)m * DD + col] = v;
                }
            }
        }
    }
}

__global__ __launch_bounds__(256) void qkv_proj(
    const float* __restrict__ Q, const float* __restrict__ K, const float* __restrict__ V,
    const float* __restrict__ Wq, const float* __restrict__ bq,
    const float* __restrict__ Wk, const float* __restrict__ bk,
    const float* __restrict__ Wv, const float* __restrict__ bv,
    float* __restrict__ oq, float* __restrict__ ok, float* __restrict__ ov)
{
    const float *X, *W, *bias; float* out;
    if (blockIdx.z == 0)      { X = Q; W = Wq; bias = bq; out = oq; }
    else if (blockIdx.z == 1) { X = K; W = Wk; bias = bk; out = ok; }
    else                      { X = V; W = Wv; bias = bv; out = ov; }
    proj_body(X, W, bias, out, 1, blockIdx.y * 128, blockIdx.x * 128);
}

__global__ __launch_bounds__(256) void proj_mma(
    const float* __restrict__ X, const float* __restrict__ W,
    const float* __restrict__ bias, float* __restrict__ out, int scatter)
{
    proj_body(X, W, bias, out, scatter, blockIdx.y * 128, blockIdx.x * 128);
}

// ---------------------------------------------------------------------------
// Two-pass fused attention at 64x64 granularity for 3 blocks/SM.
// Block owns (bh, 64 q-rows). 256 thr, 8 warps (2m x 4n), warp tile 32x16.
// smem words: Qs[64*68] | Ks[64*68] | Vs[64*72] | Ps[64*68] | rowsum[64]
// ---------------------------------------------------------------------------
#define QS_OFF   0
#define KS_OFF   4352
#define VS_OFF   8704
#define PS_OFF   13312
#define RS_OFF   17664
#define ATTN_SMEM_W 17728   // 70,912 B -> 3 blocks/SM

__global__ __launch_bounds__(256, 3) void attn_fused(float* __restrict__ dist)
{
    extern __shared__ unsigned sm[];
    unsigned* Qs = sm + QS_OFF;
    unsigned* Ks = sm + KS_OFF;
    unsigned* Vs = sm + VS_OFF;
    unsigned* Ps = sm + PS_OFF;
    float* rowsum = (float*)(sm + RS_OFF);

    const int t = threadIdx.x;
    const int warp = t >> 5, lane = t & 31;
    const int wm = warp >> 2, wn = warp & 3;   // 2m x 4n
    const int g = lane >> 2, tig = lane & 3;
    const int bh = blockIdx.y, b = bh >> 3, h = bh & 7;
    const int m0 = blockIdx.x * 64;

    const float* q = g_q + (size_t)bh * SS * HD;
    const float* k = g_k + (size_t)bh * SS * HD;
    const float* v = g_v + (size_t)bh * SS * HD;

    // load Q tile (64x64, resident tf32)
    #pragma unroll
    for (int i = 0; i < 4; i++) {
        int f = i * 256 + t;
        int r = f >> 4, c4 = (f & 15) * 4;
        float4 qv = *(const float4*)&q[(size_t)(m0 + r) * HD + c4];
        *(uint4*)&Qs[r * 68 + c4] = make_uint4(f2tf(qv.x), f2tf(qv.y), f2tf(qv.z), f2tf(qv.w));
    }
    if (t < 64) rowsum[t] = 0.0f;

    float rs[2][2] = {};

    // ======== Phase A: row sums ========
    for (int it = 0; it < 32; it++) {
        const int n0 = it * 64;
        __syncthreads();
        #pragma unroll
        for (int i = 0; i < 4; i++) {
            int f = i * 256 + t;
            int r = f >> 4, c4 = (f & 15) * 4;
            float4 kv = *(const float4*)&k[(size_t)(n0 + r) * HD + c4];
            *(uint4*)&Ks[r * 68 + c4] = make_uint4(f2tf(kv.x), f2tf(kv.y), f2tf(kv.z), f2tf(kv.w));
        }
        __syncthreads();

        float acc[2][2][4] = {};
        #pragma unroll
        for (int kk = 0; kk < 64; kk += 8) {
            unsigned af[2][4], bf[2][2];
            #pragma unroll
            for (int mt = 0; mt < 2; mt++) {
                int mrow = wm * 32 + mt * 16;
                af[mt][0] = Qs[(mrow + g) * 68 + kk + tig];
                af[mt][1] = Qs[(mrow + g + 8) * 68 + kk + tig];
                af[mt][2] = Qs[(mrow + g) * 68 + kk + tig + 4];
                af[mt][3] = Qs[(mrow + g + 8) * 68 + kk + tig + 4];
            }
            #pragma unroll
            for (int nt = 0; nt < 2; nt++) {
                int ncol = wn * 16 + nt * 8 + g;
                bf[nt][0] = Ks[ncol * 68 + kk + tig];
                bf[nt][1] = Ks[ncol * 68 + kk + tig + 4];
            }
            #pragma unroll
            for (int mt = 0; mt < 2; mt++)
                #pragma unroll
                for (int nt = 0; nt < 2; nt++)
                    mma_tf32(acc[mt][nt], af[mt], bf[nt]);
        }

        #pragma unroll
        for (int mt = 0; mt < 2; mt++) {
            #pragma unroll
            for (int half = 0; half < 2; half++) {
                int row = m0 + wm * 32 + mt * 16 + g + half * 8;
                unsigned mb = g_mbits[((size_t)b * SS + row) * (SS/32) + (n0 >> 5) + (wn >> 1)];
                int bitbase = (wn & 1) * 16;
                #pragma unroll
                for (int nt = 0; nt < 2; nt++) {
                    int nloc = nt * 8 + 2 * tig;
                    float e0 = ((mb >> (bitbase + nloc)) & 1u) ? 0.0f : __expf(acc[mt][nt][half*2+0] * 0.125f);
                    float e1 = ((mb >> (bitbase + nloc + 1)) & 1u) ? 0.0f : __expf(acc[mt][nt][half*2+1] * 0.125f);
                    rs[mt][half] += e0 + e1;
                }
            }
        }
    }

    // reduce row sums across quads + the 4 n-warps
    #pragma unroll
    for (int mt = 0; mt < 2; mt++)
        #pragma unroll
        for (int half = 0; half < 2; half++) {
            float s = rs[mt][half];
            s += __shfl_xor_sync(0xffffffffu, s, 1);
            s += __shfl_xor_sync(0xffffffffu, s, 2);
            if (tig == 0)
                atomicAdd(&rowsum[wm * 32 + mt * 16 + g + half * 8], s);
        }
    __syncthreads();
    if (t < 64) rowsum[t] = 1.0f / rowsum[t];

    // ======== Phase B: recompute, write normalized dist once, PV ========
    float y[2][2][4] = {};
    const size_t dbase = (size_t)bh * SS * SS;

    for (int it = 0; it < 32; it++) {
        const int n0 = it * 64;
        __syncthreads();   // prev PV reads done; rowsum published on it==0
        #pragma unroll
        for (int i = 0; i < 4; i++) {
            int f = i * 256 + t;
            int r = f >> 4, c4 = (f & 15) * 4;
            float4 kv = *(const float4*)&k[(size_t)(n0 + r) * HD + c4];
            *(uint4*)&Ks[r * 68 + c4] = make_uint4(f2tf(kv.x), f2tf(kv.y), f2tf(kv.z), f2tf(kv.w));
            float4 vv = *(const float4*)&v[(size_t)(n0 + r) * HD + c4];
            *(uint4*)&Vs[r * 72 + c4] = make_uint4(f2tf(vv.x), f2tf(vv.y), f2tf(vv.z), f2tf(vv.w));
        }
        __syncthreads();

        float acc[2][2][4] = {};
        #pragma unroll
        for (int kk = 0; kk < 64; kk += 8) {
            unsigned af[2][4], bf[2][2];
            #pragma unroll
            for (int mt = 0; mt < 2; mt++) {
                int mrow = wm * 32 + mt * 16;
                af[mt][0] = Qs[(mrow + g) * 68 + kk + tig];
                af[mt][1] = Qs[(mrow + g + 8) * 68 + kk + tig];
                af[mt][2] = Qs[(mrow + g) * 68 + kk + tig + 4];
                af[mt][3] = Qs[(mrow + g + 8) * 68 + kk + tig + 4];
            }
            #pragma unroll
            for (int nt = 0; nt < 2; nt++) {
                int ncol = wn * 16 + nt * 8 + g;
                bf[nt][0] = Ks[ncol * 68 + kk + tig];
                bf[nt][1] = Ks[ncol * 68 + kk + tig + 4];
            }
            #pragma unroll
            for (int mt = 0; mt < 2; mt++)
                #pragma unroll
                for (int nt = 0; nt < 2; nt++)
                    mma_tf32(acc[mt][nt], af[mt], bf[nt]);
        }

        // epilogue: normalize, write dist once, deposit tf32 P
        #pragma unroll
        for (int mt = 0; mt < 2; mt++) {
            #pragma unroll
            for (int half = 0; half < 2; half++) {
                int rowl = wm * 32 + mt * 16 + g + half * 8;
                int row = m0 + rowl;
                unsigned mb = g_mbits[((size_t)b * SS + row) * (SS/32) + (n0 >> 5) + (wn >> 1)];
                int bitbase = (wn & 1) * 16;
                float inv = rowsum[rowl];
                #pragma unroll
                for (int nt = 0; nt < 2; nt++) {
                    int nloc = nt * 8 + 2 * tig;
                    float e0 = ((mb >> (bitbase + nloc)) & 1u) ? 0.0f : __expf(acc[mt][nt][half*2+0] * 0.125f) * inv;
                    float e1 = ((mb >> (bitbase + nloc + 1)) & 1u) ? 0.0f : __expf(acc[mt][nt][half*2+1] * 0.125f) * inv;
                    float2 ev; ev.x = e0; ev.y = e1;
                    *(float2*)&dist[dbase + (size_t)row * SS + n0 + wn * 16 + nloc] = ev;
                    uint2 pv; pv.x = f2tf(e0); pv.y = f2tf(e1);
                    *(uint2*)&Ps[rowl * 68 + wn * 16 + nloc] = pv;
                }
            }
        }
        __syncthreads();   // Ps visible

        // PV: y += P[64x64] @ V[64x64]; warp tile 32x16
        #pragma unroll
        for (int kk = 0; kk < 64; kk += 8) {
            unsigned af[2][4], bf[2][2];
            #pragma unroll
            for (int mt = 0; mt < 2; mt++) {
                int mrow = wm * 32 + mt * 16;
                af[mt][0] = Ps[(mrow + g) * 68 + kk + tig];
                af[mt][1] = Ps[(mrow + g + 8) * 68 + kk + tig];
                af[mt][2] = Ps[(mrow + g) * 68 + kk + tig + 4];
                af[mt][3] = Ps[(mrow + g + 8) * 68 + kk + tig + 4];
            }
            #pragma unroll
            for (int nt = 0; nt < 2; nt++) {
                int ncol = wn * 16 + nt * 8 + g;
                bf[nt][0] = Vs[(kk + tig) * 72 + ncol];
                bf[nt][1] = Vs[(kk + tig + 4) * 72 + ncol];
            }
            #pragma unroll
            for (int mt = 0; mt < 2; mt++)
                #pragma unroll
                for (int nt = 0; nt < 2; nt++)
                    mma_tf32(y[mt][nt], af[mt], bf[nt]);
        }
    }

    // write x (P was normalized, so y is final)
    #pragma unroll
    for (int mt = 0; mt < 2; mt++) {
        #pragma unroll
        for (int nt = 0; nt < 2; nt++) {
            #pragma unroll
            for (int half = 0; half < 2; half++) {
                int row = m0 + wm * 32 + mt * 16 + g + half * 8;
                int col = wn * 16 + nt * 8 + 2 * tig;
                float2 o;
                o.x = y[mt][nt][half * 2 + 0];
                o.y = y[mt][nt][half * 2 + 1];
                *(float2*)&g_x[((size_t)(b * SS + row)) * DD + h * HD + col] = o;
            }
        }
    }
}

// ---------------------------------------------------------------------------
extern "C" void kernel_launch(void* const* d_in, const int* in_sizes, int n_in,
                              void* d_out, int out_size)
{
    const float* Q  = (const float*)d_in[0];
    const float* K  = (const float*)d_in[1];
    const float* V  = (const float*)d_in[2];
    const int*   mask = (const int*)d_in[3];
    const float* Wq = (const float*)d_in[4];
    const float* bq = (const float*)d_in[5];
    const float* Wk = (const float*)d_in[6];
    const float* bk = (const float*)d_in[7];
    const float* Wv = (const float*)d_in[8];
    const float* bv = (const float*)d_in[9];
    const float* Wo = (const float*)d_in[10];
    const float* bo = (const float*)d_in[11];

    float* out_x    = (float*)d_out;
    float* out_dist = (float*)d_out + (size_t)BB * SS * DD;

    void* pq; void* pk; void* pv; void* px; void* pbits;
    cudaGetSymbolAddress(&pq, g_q);
    cudaGetSymbolAddress(&pk, g_k);
    cudaGetSymbolAddress(&pv, g_v);
    cudaGetSymbolAddress(&px, g_x);
    cudaGetSymbolAddress(&pbits, g_mbits);

    const int ATTN_SMEM = ATTN_SMEM_W * 4;     // 70,912 B
    cudaFuncSetAttribute(attn_fused, cudaFuncAttributeMaxDynamicSharedMemorySize, ATTN_SMEM);

    pack_mask_kernel<<<(BB * SS * (SS/32)) / 256, 256>>>(mask, (unsigned*)pbits);

    dim3 gqkv(DD / 128, (BB * SS) / 128, 3);                // (4, 64, 3)
    qkv_proj<<<gqkv, 256>>>(Q, K, V, Wq, bq, Wk, bk, Wv, bv,
                            (float*)pq, (float*)pk, (float*)pv);

    dim3 gattn(SS / 64, BH);                                // (32, 32)
    attn_fused<<<gattn, 256, ATTN_SMEM>>>(out_dist);

    dim3 gproj(DD / 128, (BB * SS) / 128);                  // (4, 64)
    proj_mma<<<gproj, 256>>>((const float*)px, Wo, bo, out_x, 0);
}

// round 12
// speedup vs baseline: 1.6809x; 1.2477x over previous
#include <cuda_runtime.h>
#include <cuda_fp16.h>
#include <cstdint>
#include <math.h>

#define BB 4
#define SS 2048
#define DD 512
#define HH 8
#define HD 64
#define BH (BB*HH)

__device__ float    g_q[BH * SS * HD];
__device__ float    g_k[BH * SS * HD];
__device__ float    g_v[BH * SS * HD];
__device__ float    g_x[BB * SS * DD];
__device__ unsigned g_mbits[BB * SS * (SS/32)];

// ---------------------------------------------------------------------------
__device__ __forceinline__ unsigned f2tf(float x) {
    unsigned r;
    asm("cvt.rna.tf32.f32 %0, %1;" : "=r"(r) : "f"(x));
    return r;
}
__device__ __forceinline__ void mma_tf32(float c[4], const unsigned a[4], const unsigned b[2]) {
    asm volatile(
        "mma.sync.aligned.m16n8k8.row.col.f32.tf32.tf32.f32 "
        "{%0,%1,%2,%3},{%4,%5,%6,%7},{%8,%9},{%0,%1,%2,%3};"
        : "+f"(c[0]), "+f"(c[1]), "+f"(c[2]), "+f"(c[3])
        : "r"(a[0]), "r"(a[1]), "r"(a[2]), "r"(a[3]), "r"(b[0]), "r"(b[1]));
}
// fp16 HMMA: 2x MACs per instruction vs tf32, same 10-bit mantissa.
__device__ __forceinline__ void mma_f16(float c[4], const unsigned a[4], const unsigned b[2]) {
    asm volatile(
        "mma.sync.aligned.m16n8k16.row.col.f32.f16.f16.f32 "
        "{%0,%1,%2,%3},{%4,%5,%6,%7},{%8,%9},{%0,%1,%2,%3};"
        : "+f"(c[0]), "+f"(c[1]), "+f"(c[2]), "+f"(c[3])
        : "r"(a[0]), "r"(a[1]), "r"(a[2]), "r"(a[3]), "r"(b[0]), "r"(b[1]));
}
// ldmatrix x4 transposed b16: B-fragments for PV from [k][n]-stored V.
__device__ __forceinline__ void ldmx4t(unsigned r[4], const __half* p) {
    unsigned a = (unsigned)__cvta_generic_to_shared(p);
    asm volatile("ldmatrix.sync.aligned.m8n8.x4.trans.shared.b16 {%0,%1,%2,%3}, [%4];"
        : "=r"(r[0]), "=r"(r[1]), "=r"(r[2]), "=r"(r[3]) : "r"(a));
}
__device__ __forceinline__ unsigned h2u(__half2 h) { return *(unsigned*)&h; }

// ---------------------------------------------------------------------------
__global__ __launch_bounds__(256) void pack_mask_kernel(
    const int* __restrict__ mask, unsigned* __restrict__ bits)
{
    int w = blockIdx.x * 256 + threadIdx.x;
    const int4* p = (const int4*)(mask + (size_t)w * 32);
    unsigned v = 0;
    #pragma unroll
    for (int i = 0; i < 8; i++) {
        int4 q = p[i];
        v |= (unsigned)(q.x != 0) << (i * 4 + 0);
        v |= (unsigned)(q.y != 0) << (i * 4 + 1);
        v |= (unsigned)(q.z != 0) << (i * 4 + 2);
        v |= (unsigned)(q.w != 0) << (i * 4 + 3);
    }
    bits[w] = v;
}

// ---------------------------------------------------------------------------
// Projection GEMM body (R10-proven tf32): C = X @ W^T + bias.
// ---------------------------------------------------------------------------
__device__ __forceinline__ void proj_body(
    const float* __restrict__ X, const float* __restrict__ W,
    const float* __restrict__ bias, float* __restrict__ out, int scatter,
    int m0, int n0)
{
    __shared__ __align__(16) unsigned As[128 * 36];
    __shared__ __align__(16) unsigned Bs[128 * 36];

    const int t = threadIdx.x;
    const int warp = t >> 5, lane = t & 31;
    const int wm = warp >> 2, wn = warp & 3;
    const int g = lane >> 2, tig = lane & 3;

    float acc[4][4][4] = {};

    for (int k0 = 0; k0 < DD; k0 += 32) {
        #pragma unroll
        for (int i = 0; i < 4; i++) {
            int f = i * 256 + t;
            int r = f >> 3, c4 = (f & 7) * 4;
            float4 xv = *(const float4*)&X[(size_t)(m0 + r) * DD + k0 + c4];
            *(uint4*)&As[r * 36 + c4] = make_uint4(f2tf(xv.x), f2tf(xv.y), f2tf(xv.z), f2tf(xv.w));
            float4 wv = *(const float4*)&W[(size_t)(n0 + r) * DD + k0 + c4];
            *(uint4*)&Bs[r * 36 + c4] = make_uint4(f2tf(wv.x), f2tf(wv.y), f2tf(wv.z), f2tf(wv.w));
        }
        __syncthreads();

        #pragma unroll
        for (int kk = 0; kk < 32; kk += 8) {
            unsigned af[4][4], bf[4][2];
            #pragma unroll
            for (int mt = 0; mt < 4; mt++) {
                int mrow = wm * 64 + mt * 16;
                af[mt][0] = As[(mrow + g) * 36 + kk + tig];
                af[mt][1] = As[(mrow + g + 8) * 36 + kk + tig];
                af[mt][2] = As[(mrow + g) * 36 + kk + tig + 4];
                af[mt][3] = As[(mrow + g + 8) * 36 + kk + tig + 4];
            }
            #pragma unroll
            for (int nt = 0; nt < 4; nt++) {
                int ncol = wn * 32 + nt * 8 + g;
                bf[nt][0] = Bs[ncol * 36 + kk + tig];
                bf[nt][1] = Bs[ncol * 36 + kk + tig + 4];
            }
            #pragma unroll
            for (int mt = 0; mt < 4; mt++)
                #pragma unroll
                for (int nt = 0; nt < 4; nt++)
                    mma_tf32(acc[mt][nt], af[mt], bf[nt]);
        }
        __syncthreads();
    }

    #pragma unroll
    for (int nt = 0; nt < 4; nt++) {
        const int col = n0 + wn * 32 + nt * 8 + 2 * tig;
        const float b0v = bias[col], b1v = bias[col + 1];
        #pragma unroll
        for (int mt = 0; mt < 4; mt++) {
            #pragma unroll
            for (int half = 0; half < 2; half++) {
                int m = m0 + wm * 64 + mt * 16 + g + half * 8;
                float2 v;
                v.x = acc[mt][nt][half * 2 + 0] + b0v;
                v.y = acc[mt][nt][half * 2 + 1] + b1v;
                if (scatter) {
                    int b = m >> 11, s = m & (SS - 1);
                    int h = col >> 6, hd = col & (HD - 1);
                    *(float2*)&out[(((size_t)(b * HH + h)) * SS + s) * HD + hd] = v;
                } else {
                    *(float2*)&out[(size_t)m * DD + col] = v;
                }
            }
        }
    }
}

__global__ __launch_bounds__(256) void qkv_proj(
    const float* __restrict__ Q, const float* __restrict__ K, const float* __restrict__ V,
    const float* __restrict__ Wq, const float* __restrict__ bq,
    const float* __restrict__ Wk, const float* __restrict__ bk,
    const float* __restrict__ Wv, const float* __restrict__ bv,
    float* __restrict__ oq, float* __restrict__ ok, float* __restrict__ ov)
{
    const float *X, *W, *bias; float* out;
    if (blockIdx.z == 0)      { X = Q; W = Wq; bias = bq; out = oq; }
    else if (blockIdx.z == 1) { X = K; W = Wk; bias = bk; out = ok; }
    else                      { X = V; W = Wv; bias = bv; out = ov; }
    proj_body(X, W, bias, out, 1, blockIdx.y * 128, blockIdx.x * 128);
}

__global__ __launch_bounds__(256) void proj_mma(
    const float* __restrict__ X, const float* __restrict__ W,
    const float* __restrict__ bias, float* __restrict__ out, int scatter)
{
    proj_body(X, W, bias, out, scatter, blockIdx.y * 128, blockIdx.x * 128);
}

// ---------------------------------------------------------------------------
// Two-pass fused attention, fp16 HMMA. 64x64 tiles, 3 blocks/SM.
// smem (halfs): Qs[64*72] | Ks[64*72] | Vs[64*72] | Ps[64*72] | rowsum(64 f32)
// ---------------------------------------------------------------------------
#define HQS 0
#define HKS 4608
#define HVS 9216
#define HPS 13824
#define HRS 18432
#define ATTN_SMEM_B ((18432 + 128) * 2)   // 37,120 B

__global__ __launch_bounds__(256, 3) void attn_fused(float* __restrict__ dist)
{
    extern __shared__ __half hsm[];
    __half* Qs = hsm + HQS;
    __half* Ks = hsm + HKS;
    __half* Vs = hsm + HVS;
    __half* Ps = hsm + HPS;
    float* rowsum = (float*)(hsm + HRS);

    const int t = threadIdx.x;
    const int warp = t >> 5, lane = t & 31;
    const int wm = warp >> 2, wn = warp & 3;   // 2m x 4n, warp tile 32x16
    const int g = lane >> 2, tig = lane & 3;
    const int bh = blockIdx.y, b = bh >> 3, h = bh & 7;
    const int m0 = blockIdx.x * 64;

    const float* q = g_q + (size_t)bh * SS * HD;
    const float* k = g_k + (size_t)bh * SS * HD;
    const float* v = g_v + (size_t)bh * SS * HD;

    // load Q tile (64x64 half, resident)
    #pragma unroll
    for (int i = 0; i < 4; i++) {
        int id = i * 256 + t;
        int r = id >> 4, c4 = (id & 15) * 4;
        float4 qv = *(const float4*)&q[(size_t)(m0 + r) * HD + c4];
        *(uint2*)&Qs[r * 72 + c4] = make_uint2(
            h2u(__floats2half2_rn(qv.x, qv.y)), h2u(__floats2half2_rn(qv.z, qv.w)));
    }
    if (t < 64) rowsum[t] = 0.0f;

    float rs[2][2] = {};

    // ======== Phase A: row sums ========
    for (int it = 0; it < 32; it++) {
        const int n0 = it * 64;
        __syncthreads();
        #pragma unroll
        for (int i = 0; i < 4; i++) {
            int id = i * 256 + t;
            int r = id >> 4, c4 = (id & 15) * 4;
            float4 kv = *(const float4*)&k[(size_t)(n0 + r) * HD + c4];
            *(uint2*)&Ks[r * 72 + c4] = make_uint2(
                h2u(__floats2half2_rn(kv.x, kv.y)), h2u(__floats2half2_rn(kv.z, kv.w)));
        }
        __syncthreads();

        float acc[2][2][4] = {};
        #pragma unroll
        for (int kk = 0; kk < 64; kk += 16) {
            unsigned af[2][4], bf[2][2];
            #pragma unroll
            for (int mt = 0; mt < 2; mt++) {
                int mrow = wm * 32 + mt * 16;
                af[mt][0] = *(unsigned*)&Qs[(mrow + g) * 72 + kk + 2 * tig];
                af[mt][1] = *(unsigned*)&Qs[(mrow + g + 8) * 72 + kk + 2 * tig];
                af[mt][2] = *(unsigned*)&Qs[(mrow + g) * 72 + kk + 2 * tig + 8];
                af[mt][3] = *(unsigned*)&Qs[(mrow + g + 8) * 72 + kk + 2 * tig + 8];
            }
            #pragma unroll
            for (int nt = 0; nt < 2; nt++) {
                int ncol = wn * 16 + nt * 8 + g;
                bf[nt][0] = *(unsigned*)&Ks[ncol * 72 + kk + 2 * tig];
                bf[nt][1] = *(unsigned*)&Ks[ncol * 72 + kk + 2 * tig + 8];
            }
            #pragma unroll
            for (int mt = 0; mt < 2; mt++)
                #pragma unroll
                for (int nt = 0; nt < 2; nt++)
                    mma_f16(acc[mt][nt], af[mt], bf[nt]);
        }

        #pragma unroll
        for (int mt = 0; mt < 2; mt++) {
            #pragma unroll
            for (int half = 0; half < 2; half++) {
                int row = m0 + wm * 32 + mt * 16 + g + half * 8;
                unsigned mb = g_mbits[((size_t)b * SS + row) * (SS/32) + (n0 >> 5) + (wn >> 1)];
                int bitbase = (wn & 1) * 16;
                #pragma unroll
                for (int nt = 0; nt < 2; nt++) {
                    int nloc = nt * 8 + 2 * tig;
                    float e0 = ((mb >> (bitbase + nloc)) & 1u) ? 0.0f : __expf(acc[mt][nt][half*2+0] * 0.125f);
                    float e1 = ((mb >> (bitbase + nloc + 1)) & 1u) ? 0.0f : __expf(acc[mt][nt][half*2+1] * 0.125f);
                    rs[mt][half] += e0 + e1;
                }
            }
        }
    }

    // reduce row sums
    #pragma unroll
    for (int mt = 0; mt < 2; mt++)
        #pragma unroll
        for (int half = 0; half < 2; half++) {
            float s = rs[mt][half];
            s += __shfl_xor_sync(0xffffffffu, s, 1);
            s += __shfl_xor_sync(0xffffffffu, s, 2);
            if (tig == 0)
                atomicAdd(&rowsum[wm * 32 + mt * 16 + g + half * 8], s);
        }
    __syncthreads();
    if (t < 64) rowsum[t] = 1.0f / rowsum[t];

    // ======== Phase B: recompute, write normalized dist once, PV ========
    float y[2][2][4] = {};
    const size_t dbase = (size_t)bh * SS * SS;

    for (int it = 0; it < 32; it++) {
        const int n0 = it * 64;
        __syncthreads();
        #pragma unroll
        for (int i = 0; i < 4; i++) {
            int id = i * 256 + t;
            int r = id >> 4, c4 = (id & 15) * 4;
            float4 kv = *(const float4*)&k[(size_t)(n0 + r) * HD + c4];
            *(uint2*)&Ks[r * 72 + c4] = make_uint2(
                h2u(__floats2half2_rn(kv.x, kv.y)), h2u(__floats2half2_rn(kv.z, kv.w)));
            float4 vv = *(const float4*)&v[(size_t)(n0 + r) * HD + c4];
            *(uint2*)&Vs[r * 72 + c4] = make_uint2(
                h2u(__floats2half2_rn(vv.x, vv.y)), h2u(__floats2half2_rn(vv.z, vv.w)));
        }
        __syncthreads();

        float acc[2][2][4] = {};
        #pragma unroll
        for (int kk = 0; kk < 64; kk += 16) {
            unsigned af[2][4], bf[2][2];
            #pragma unroll
            for (int mt = 0; mt < 2; mt++) {
                int mrow = wm * 32 + mt * 16;
                af[mt][0] = *(unsigned*)&Qs[(mrow + g) * 72 + kk + 2 * tig];
                af[mt][1] = *(unsigned*)&Qs[(mrow + g + 8) * 72 + kk + 2 * tig];
                af[mt][2] = *(unsigned*)&Qs[(mrow + g) * 72 + kk + 2 * tig + 8];
                af[mt][3] = *(unsigned*)&Qs[(mrow + g + 8) * 72 + kk + 2 * tig + 8];
            }
            #pragma unroll
            for (int nt = 0; nt < 2; nt++) {
                int ncol = wn * 16 + nt * 8 + g;
                bf[nt][0] = *(unsigned*)&Ks[ncol * 72 + kk + 2 * tig];
                bf[nt][1] = *(unsigned*)&Ks[ncol * 72 + kk + 2 * tig + 8];
            }
            #pragma unroll
            for (int mt = 0; mt < 2; mt++)
                #pragma unroll
                for (int nt = 0; nt < 2; nt++)
                    mma_f16(acc[mt][nt], af[mt], bf[nt]);
        }

        // epilogue: normalize, write dist once, deposit fp16 P
        #pragma unroll
        for (int mt = 0; mt < 2; mt++) {
            #pragma unroll
            for (int half = 0; half < 2; half++) {
                int rowl = wm * 32 + mt * 16 + g + half * 8;
                int row = m0 + rowl;
                unsigned mb = g_mbits[((size_t)b * SS + row) * (SS/32) + (n0 >> 5) + (wn >> 1)];
                int bitbase = (wn & 1) * 16;
                float inv = rowsum[rowl];
                #pragma unroll
                for (int nt = 0; nt < 2; nt++) {
                    int nloc = nt * 8 + 2 * tig;
                    float e0 = ((mb >> (bitbase + nloc)) & 1u) ? 0.0f : __expf(acc[mt][nt][half*2+0] * 0.125f) * inv;
                    float e1 = ((mb >> (bitbase + nloc + 1)) & 1u) ? 0.0f : __expf(acc[mt][nt][half*2+1] * 0.125f) * inv;
                    float2 ev; ev.x = e0; ev.y = e1;
                    *(float2*)&dist[dbase + (size_t)row * SS + n0 + wn * 16 + nloc] = ev;
                    *(unsigned*)&Ps[rowl * 72 + wn * 16 + nloc] = h2u(__floats2half2_rn(e0, e1));
                }
            }
        }
        __syncthreads();   // Ps/Vs visible

        // PV: y += P[64x64] @ V[64x64]; B-frags via ldmatrix.x4.trans
        #pragma unroll
        for (int kk = 0; kk < 64; kk += 16) {
            unsigned af[2][4], bv[4];
            #pragma unroll
            for (int mt = 0; mt < 2; mt++) {
                int mrow = wm * 32 + mt * 16;
                af[mt][0] = *(unsigned*)&Ps[(mrow + g) * 72 + kk + 2 * tig];
                af[mt][1] = *(unsigned*)&Ps[(mrow + g + 8) * 72 + kk + 2 * tig];
                af[mt][2] = *(unsigned*)&Ps[(mrow + g) * 72 + kk + 2 * tig + 8];
                af[mt][3] = *(unsigned*)&Ps[(mrow + g + 8) * 72 + kk + 2 * tig + 8];
            }
            ldmx4t(bv, &Vs[(kk + (lane & 15)) * 72 + wn * 16 + (lane >> 4) * 8]);
            #pragma unroll
            for (int mt = 0; mt < 2; mt++) {
                mma_f16(y[mt][0], af[mt], bv + 0);
                mma_f16(y[mt][1], af[mt], bv + 2);
            }
        }
    }

    // write x (P normalized, so y final)
    #pragma unroll
    for (int mt = 0; mt < 2; mt++) {
        #pragma unroll
        for (int nt = 0; nt < 2; nt++) {
            #pragma unroll
            for (int half = 0; half < 2; half++) {
                int row = m0 + wm * 32 + mt * 16 + g + half * 8;
                int col = wn * 16 + nt * 8 + 2 * tig;
                float2 o;
                o.x = y[mt][nt][half * 2 + 0];
                o.y = y[mt][nt][half * 2 + 1];
                *(float2*)&g_x[((size_t)(b * SS + row)) * DD + h * HD + col] = o;
            }
        }
    }
}

// ---------------------------------------------------------------------------
extern "C" void kernel_launch(void* const* d_in, const int* in_sizes, int n_in,
                              void* d_out, int out_size)
{
    const float* Q  = (const float*)d_in[0];
    const float* K  = (const float*)d_in[1];
    const float* V  = (const float*)d_in[2];
    const int*   mask = (const int*)d_in[3];
    const float* Wq = (const float*)d_in[4];
    const float* bq = (const float*)d_in[5];
    const float* Wk = (const float*)d_in[6];
    const float* bk = (const float*)d_in[7];
    const float* Wv = (const float*)d_in[8];
    const float* bv = (const float*)d_in[9];
    const float* Wo = (const float*)d_in[10];
    const float* bo = (const float*)d_in[11];

    float* out_x    = (float*)d_out;
    float* out_dist = (float*)d_out + (size_t)BB * SS * DD;

    void* pq; void* pk; void* pv; void* px; void* pbits;
    cudaGetSymbolAddress(&pq, g_q);
    cudaGetSymbolAddress(&pk, g_k);
    cudaGetSymbolAddress(&pv, g_v);
    cudaGetSymbolAddress(&px, g_x);
    cudaGetSymbolAddress(&pbits, g_mbits);

    cudaFuncSetAttribute(attn_fused, cudaFuncAttributeMaxDynamicSharedMemorySize, ATTN_SMEM_B);

    pack_mask_kernel<<<(BB * SS * (SS/32)) / 256, 256>>>(mask, (unsigned*)pbits);

    dim3 gqkv(DD / 128, (BB * SS) / 128, 3);                // (4, 64, 3)
    qkv_proj<<<gqkv, 256>>>(Q, K, V, Wq, bq, Wk, bk, Wv, bv,
                            (float*)pq, (float*)pk, (float*)pv);

    dim3 gattn(SS / 64, BH);                                // (32, 32)
    attn_fused<<<gattn, 256, ATTN_SMEM_B>>>(out_dist);

    dim3 gproj(DD / 128, (BB * SS) / 128);                  // (4, 64)
    proj_mma<<<gproj, 256>>>((const float*)px, Wo, bo, out_x, 0);
}

// round 13
// speedup vs baseline: 1.6998x; 1.0113x over previous
#include <cuda_runtime.h>
#include <cuda_fp16.h>
#include <cstdint>
#include <math.h>

#define BB 4
#define SS 2048
#define DD 512
#define HH 8
#define HD 64
#define BH (BB*HH)

__device__ float    g_q[BH * SS * HD];
__device__ float    g_k[BH * SS * HD];
__device__ float    g_v[BH * SS * HD];
__device__ float    g_x[BB * SS * DD];
__device__ unsigned g_mbits[BB * SS * (SS/32)];

// ---------------------------------------------------------------------------
// fp16 HMMA m16n8k16, fp32 accumulate
__device__ __forceinline__ void mma_f16(float c[4], const unsigned a[4], const unsigned b[2]) {
    asm volatile(
        "mma.sync.aligned.m16n8k16.row.col.f32.f16.f16.f32 "
        "{%0,%1,%2,%3},{%4,%5,%6,%7},{%8,%9},{%0,%1,%2,%3};"
        : "+f"(c[0]), "+f"(c[1]), "+f"(c[2]), "+f"(c[3])
        : "r"(a[0]), "r"(a[1]), "r"(a[2]), "r"(a[3]), "r"(b[0]), "r"(b[1]));
}
__device__ __forceinline__ void ldmx4t(unsigned r[4], const __half* p) {
    unsigned a = (unsigned)__cvta_generic_to_shared(p);
    asm volatile("ldmatrix.sync.aligned.m8n8.x4.trans.shared.b16 {%0,%1,%2,%3}, [%4];"
        : "=r"(r[0]), "=r"(r[1]), "=r"(r[2]), "=r"(r[3]) : "r"(a));
}
__device__ __forceinline__ unsigned h2u(__half2 h) { return *(unsigned*)&h; }

// ---------------------------------------------------------------------------
__global__ __launch_bounds__(256) void pack_mask_kernel(
    const int* __restrict__ mask, unsigned* __restrict__ bits)
{
    int w = blockIdx.x * 256 + threadIdx.x;
    const int4* p = (const int4*)(mask + (size_t)w * 32);
    unsigned v = 0;
    #pragma unroll
    for (int i = 0; i < 8; i++) {
        int4 q = p[i];
        v |= (unsigned)(q.x != 0) << (i * 4 + 0);
        v |= (unsigned)(q.y != 0) << (i * 4 + 1);
        v |= (unsigned)(q.z != 0) << (i * 4 + 2);
        v |= (unsigned)(q.w != 0) << (i * 4 + 3);
    }
    bits[w] = v;
}

// ---------------------------------------------------------------------------
// Projection GEMM body, fp16 HMMA: C = X @ W^T + bias.
// Block 128x128, 256 thr, 8 warps (2m x 4n, warp 64x32), k-tile 64.
// ---------------------------------------------------------------------------
__device__ __forceinline__ void proj_body(
    const float* __restrict__ X, const float* __restrict__ W,
    const float* __restrict__ bias, float* __restrict__ out, int scatter,
    int m0, int n0)
{
    __shared__ __align__(16) __half As[128 * 72];
    __shared__ __align__(16) __half Bs[128 * 72];

    const int t = threadIdx.x;
    const int warp = t >> 5, lane = t & 31;
    const int wm = warp >> 2, wn = warp & 3;
    const int g = lane >> 2, tig = lane & 3;

    float acc[4][4][4] = {};

    for (int k0 = 0; k0 < DD; k0 += 64) {
        #pragma unroll
        for (int i = 0; i < 8; i++) {
            int id = i * 256 + t;
            int r = id >> 4, c4 = (id & 15) * 4;
            float4 xv = *(const float4*)&X[(size_t)(m0 + r) * DD + k0 + c4];
            *(uint2*)&As[r * 72 + c4] = make_uint2(
                h2u(__floats2half2_rn(xv.x, xv.y)), h2u(__floats2half2_rn(xv.z, xv.w)));
            float4 wv = *(const float4*)&W[(size_t)(n0 + r) * DD + k0 + c4];
            *(uint2*)&Bs[r * 72 + c4] = make_uint2(
                h2u(__floats2half2_rn(wv.x, wv.y)), h2u(__floats2half2_rn(wv.z, wv.w)));
        }
        __syncthreads();

        #pragma unroll
        for (int kk = 0; kk < 64; kk += 16) {
            unsigned af[4][4], bf[4][2];
            #pragma unroll
            for (int mt = 0; mt < 4; mt++) {
                int mrow = wm * 64 + mt * 16;
                af[mt][0] = *(unsigned*)&As[(mrow + g) * 72 + kk + 2 * tig];
                af[mt][1] = *(unsigned*)&As[(mrow + g + 8) * 72 + kk + 2 * tig];
                af[mt][2] = *(unsigned*)&As[(mrow + g) * 72 + kk + 2 * tig + 8];
                af[mt][3] = *(unsigned*)&As[(mrow + g + 8) * 72 + kk + 2 * tig + 8];
            }
            #pragma unroll
            for (int nt = 0; nt < 4; nt++) {
                int ncol = wn * 32 + nt * 8 + g;
                bf[nt][0] = *(unsigned*)&Bs[ncol * 72 + kk + 2 * tig];
                bf[nt][1] = *(unsigned*)&Bs[ncol * 72 + kk + 2 * tig + 8];
            }
            #pragma unroll
            for (int mt = 0; mt < 4; mt++)
                #pragma unroll
                for (int nt = 0; nt < 4; nt++)
                    mma_f16(acc[mt][nt], af[mt], bf[nt]);
        }
        __syncthreads();
    }

    #pragma unroll
    for (int nt = 0; nt < 4; nt++) {
        const int col = n0 + wn * 32 + nt * 8 + 2 * tig;
        const float b0v = bias[col], b1v = bias[col + 1];
        #pragma unroll
        for (int mt = 0; mt < 4; mt++) {
            #pragma unroll
            for (int half = 0; half < 2; half++) {
                int m = m0 + wm * 64 + mt * 16 + g + half * 8;
                float2 v;
                v.x = acc[mt][nt][half * 2 + 0] + b0v;
                v.y = acc[mt][nt][half * 2 + 1] + b1v;
                if (scatter) {
                    int b = m >> 11, s = m & (SS - 1);
                    int h = col >> 6, hd = col & (HD - 1);
                    *(float2*)&out[(((size_t)(b * HH + h)) * SS + s) * HD + hd] = v;
                } else {
                    *(float2*)&out[(size_t)m * DD + col] = v;
                }
            }
        }
    }
}

__global__ __launch_bounds__(256) void qkv_proj(
    const float* __restrict__ Q, const float* __restrict__ K, const float* __restrict__ V,
    const float* __restrict__ Wq, const float* __restrict__ bq,
    const float* __restrict__ Wk, const float* __restrict__ bk,
    const float* __restrict__ Wv, const float* __restrict__ bv,
    float* __restrict__ oq, float* __restrict__ ok, float* __restrict__ ov)
{
    const float *X, *W, *bias; float* out;
    if (blockIdx.z == 0)      { X = Q; W = Wq; bias = bq; out = oq; }
    else if (blockIdx.z == 1) { X = K; W = Wk; bias = bk; out = ok; }
    else                      { X = V; W = Wv; bias = bv; out = ov; }
    proj_body(X, W, bias, out, 1, blockIdx.y * 128, blockIdx.x * 128);
}

__global__ __launch_bounds__(256) void proj_mma(
    const float* __restrict__ X, const float* __restrict__ W,
    const float* __restrict__ bias, float* __restrict__ out, int scatter)
{
    proj_body(X, W, bias, out, scatter, blockIdx.y * 128, blockIdx.x * 128);
}

// ---------------------------------------------------------------------------
// Two-pass fused attention, fp16 HMMA (R12, unchanged). 64x64 tiles, 3 blk/SM.
// ---------------------------------------------------------------------------
#define HQS 0
#define HKS 4608
#define HVS 9216
#define HPS 13824
#define HRS 18432
#define ATTN_SMEM_B ((18432 + 128) * 2)   // 37,120 B

__global__ __launch_bounds__(256, 3) void attn_fused(float* __restrict__ dist)
{
    extern __shared__ __half hsm[];
    __half* Qs = hsm + HQS;
    __half* Ks = hsm + HKS;
    __half* Vs = hsm + HVS;
    __half* Ps = hsm + HPS;
    float* rowsum = (float*)(hsm + HRS);

    const int t = threadIdx.x;
    const int warp = t >> 5, lane = t & 31;
    const int wm = warp >> 2, wn = warp & 3;   // 2m x 4n, warp tile 32x16
    const int g = lane >> 2, tig = lane & 3;
    const int bh = blockIdx.y, b = bh >> 3, h = bh & 7;
    const int m0 = blockIdx.x * 64;

    const float* q = g_q + (size_t)bh * SS * HD;
    const float* k = g_k + (size_t)bh * SS * HD;
    const float* v = g_v + (size_t)bh * SS * HD;

    #pragma unroll
    for (int i = 0; i < 4; i++) {
        int id = i * 256 + t;
        int r = id >> 4, c4 = (id & 15) * 4;
        float4 qv = *(const float4*)&q[(size_t)(m0 + r) * HD + c4];
        *(uint2*)&Qs[r * 72 + c4] = make_uint2(
            h2u(__floats2half2_rn(qv.x, qv.y)), h2u(__floats2half2_rn(qv.z, qv.w)));
    }
    if (t < 64) rowsum[t] = 0.0f;

    float rs[2][2] = {};

    // ======== Phase A: row sums ========
    for (int it = 0; it < 32; it++) {
        const int n0 = it * 64;
        __syncthreads();
        #pragma unroll
        for (int i = 0; i < 4; i++) {
            int id = i * 256 + t;
            int r = id >> 4, c4 = (id & 15) * 4;
            float4 kv = *(const float4*)&k[(size_t)(n0 + r) * HD + c4];
            *(uint2*)&Ks[r * 72 + c4] = make_uint2(
                h2u(__floats2half2_rn(kv.x, kv.y)), h2u(__floats2half2_rn(kv.z, kv.w)));
        }
        __syncthreads();

        float acc[2][2][4] = {};
        #pragma unroll
        for (int kk = 0; kk < 64; kk += 16) {
            unsigned af[2][4], bf[2][2];
            #pragma unroll
            for (int mt = 0; mt < 2; mt++) {
                int mrow = wm * 32 + mt * 16;
                af[mt][0] = *(unsigned*)&Qs[(mrow + g) * 72 + kk + 2 * tig];
                af[mt][1] = *(unsigned*)&Qs[(mrow + g + 8) * 72 + kk + 2 * tig];
                af[mt][2] = *(unsigned*)&Qs[(mrow + g) * 72 + kk + 2 * tig + 8];
                af[mt][3] = *(unsigned*)&Qs[(mrow + g + 8) * 72 + kk + 2 * tig + 8];
            }
            #pragma unroll
            for (int nt = 0; nt < 2; nt++) {
                int ncol = wn * 16 + nt * 8 + g;
                bf[nt][0] = *(unsigned*)&Ks[ncol * 72 + kk + 2 * tig];
                bf[nt][1] = *(unsigned*)&Ks[ncol * 72 + kk + 2 * tig + 8];
            }
            #pragma unroll
            for (int mt = 0; mt < 2; mt++)
                #pragma unroll
                for (int nt = 0; nt < 2; nt++)
                    mma_f16(acc[mt][nt], af[mt], bf[nt]);
        }

        #pragma unroll
        for (int mt = 0; mt < 2; mt++) {
            #pragma unroll
            for (int half = 0; half < 2; half++) {
                int row = m0 + wm * 32 + mt * 16 + g + half * 8;
                unsigned mb = g_mbits[((size_t)b * SS + row) * (SS/32) + (n0 >> 5) + (wn >> 1)];
                int bitbase = (wn & 1) * 16;
                #pragma unroll
                for (int nt = 0; nt < 2; nt++) {
                    int nloc = nt * 8 + 2 * tig;
                    float e0 = ((mb >> (bitbase + nloc)) & 1u) ? 0.0f : __expf(acc[mt][nt][half*2+0] * 0.125f);
                    float e1 = ((mb >> (bitbase + nloc + 1)) & 1u) ? 0.0f : __expf(acc[mt][nt][half*2+1] * 0.125f);
                    rs[mt][half] += e0 + e1;
                }
            }
        }
    }

    #pragma unroll
    for (int mt = 0; mt < 2; mt++)
        #pragma unroll
        for (int half = 0; half < 2; half++) {
            float s = rs[mt][half];
            s += __shfl_xor_sync(0xffffffffu, s, 1);
            s += __shfl_xor_sync(0xffffffffu, s, 2);
            if (tig == 0)
                atomicAdd(&rowsum[wm * 32 + mt * 16 + g + half * 8], s);
        }
    __syncthreads();
    if (t < 64) rowsum[t] = 1.0f / rowsum[t];

    // ======== Phase B: recompute, write normalized dist once, PV ========
    float y[2][2][4] = {};
    const size_t dbase = (size_t)bh * SS * SS;

    for (int it = 0; it < 32; it++) {
        const int n0 = it * 64;
        __syncthreads();
        #pragma unroll
        for (int i = 0; i < 4; i++) {
            int id = i * 256 + t;
            int r = id >> 4, c4 = (id & 15) * 4;
            float4 kv = *(const float4*)&k[(size_t)(n0 + r) * HD + c4];
            *(uint2*)&Ks[r * 72 + c4] = make_uint2(
                h2u(__floats2half2_rn(kv.x, kv.y)), h2u(__floats2half2_rn(kv.z, kv.w)));
            float4 vv = *(const float4*)&v[(size_t)(n0 + r) * HD + c4];
            *(uint2*)&Vs[r * 72 + c4] = make_uint2(
                h2u(__floats2half2_rn(vv.x, vv.y)), h2u(__floats2half2_rn(vv.z, vv.w)));
        }
        __syncthreads();

        float acc[2][2][4] = {};
        #pragma unroll
        for (int kk = 0; kk < 64; kk += 16) {
            unsigned af[2][4], bf[2][2];
            #pragma unroll
            for (int mt = 0; mt < 2; mt++) {
                int mrow = wm * 32 + mt * 16;
                af[mt][0] = *(unsigned*)&Qs[(mrow + g) * 72 + kk + 2 * tig];
                af[mt][1] = *(unsigned*)&Qs[(mrow + g + 8) * 72 + kk + 2 * tig];
                af[mt][2] = *(unsigned*)&Qs[(mrow + g) * 72 + kk + 2 * tig + 8];
                af[mt][3] = *(unsigned*)&Qs[(mrow + g + 8) * 72 + kk + 2 * tig + 8];
            }
            #pragma unroll
            for (int nt = 0; nt < 2; nt++) {
                int ncol = wn * 16 + nt * 8 + g;
                bf[nt][0] = *(unsigned*)&Ks[ncol * 72 + kk + 2 * tig];
                bf[nt][1] = *(unsigned*)&Ks[ncol * 72 + kk + 2 * tig + 8];
            }
            #pragma unroll
            for (int mt = 0; mt < 2; mt++)
                #pragma unroll
                for (int nt = 0; nt < 2; nt++)
                    mma_f16(acc[mt][nt], af[mt], bf[nt]);
        }

        #pragma unroll
        for (int mt = 0; mt < 2; mt++) {
            #pragma unroll
            for (int half = 0; half < 2; half++) {
                int rowl = wm * 32 + mt * 16 + g + half * 8;
                int row = m0 + rowl;
                unsigned mb = g_mbits[((size_t)b * SS + row) * (SS/32) + (n0 >> 5) + (wn >> 1)];
                int bitbase = (wn & 1) * 16;
                float inv = rowsum[rowl];
                #pragma unroll
                for (int nt = 0; nt < 2; nt++) {
                    int nloc = nt * 8 + 2 * tig;
                    float e0 = ((mb >> (bitbase + nloc)) & 1u) ? 0.0f : __expf(acc[mt][nt][half*2+0] * 0.125f) * inv;
                    float e1 = ((mb >> (bitbase + nloc + 1)) & 1u) ? 0.0f : __expf(acc[mt][nt][half*2+1] * 0.125f) * inv;
                    float2 ev; ev.x = e0; ev.y = e1;
                    *(float2*)&dist[dbase + (size_t)row * SS + n0 + wn * 16 + nloc] = ev;
                    *(unsigned*)&Ps[rowl * 72 + wn * 16 + nloc] = h2u(__floats2half2_rn(e0, e1));
                }
            }
        }
        __syncthreads();

        #pragma unroll
        for (int kk = 0; kk < 64; kk += 16) {
            unsigned af[2][4], bv[4];
            #pragma unroll
            for (int mt = 0; mt < 2; mt++) {
                int mrow = wm * 32 + mt * 16;
                af[mt][0] = *(unsigned*)&Ps[(mrow + g) * 72 + kk + 2 * tig];
                af[mt][1] = *(unsigned*)&Ps[(mrow + g + 8) * 72 + kk + 2 * tig];
                af[mt][2] = *(unsigned*)&Ps[(mrow + g) * 72 + kk + 2 * tig + 8];
                af[mt][3] = *(unsigned*)&Ps[(mrow + g + 8) * 72 + kk + 2 * tig + 8];
            }
            ldmx4t(bv, &Vs[(kk + (lane & 15)) * 72 + wn * 16 + (lane >> 4) * 8]);
            #pragma unroll
            for (int mt = 0; mt < 2; mt++) {
                mma_f16(y[mt][0], af[mt], bv + 0);
                mma_f16(y[mt][1], af[mt], bv + 2);
            }
        }
    }

    #pragma unroll
    for (int mt = 0; mt < 2; mt++) {
        #pragma unroll
        for (int nt = 0; nt < 2; nt++) {
            #pragma unroll
            for (int half = 0; half < 2; half++) {
                int row = m0 + wm * 32 + mt * 16 + g + half * 8;
                int col = wn * 16 + nt * 8 + 2 * tig;
                float2 o;
                o.x = y[mt][nt][half * 2 + 0];
                o.y = y[mt][nt][half * 2 + 1];
                *(float2*)&g_x[((size_t)(b * SS + row)) * DD + h * HD + col] = o;
            }
        }
    }
}

// ---------------------------------------------------------------------------
extern "C" void kernel_launch(void* const* d_in, const int* in_sizes, int n_in,
                              void* d_out, int out_size)
{
    const float* Q  = (const float*)d_in[0];
    const float* K  = (const float*)d_in[1];
    const float* V  = (const float*)d_in[2];
    const int*   mask = (const int*)d_in[3];
    const float* Wq = (const float*)d_in[4];
    const float* bq = (const float*)d_in[5];
    const float* Wk = (const float*)d_in[6];
    const float* bk = (const float*)d_in[7];
    const float* Wv = (const float*)d_in[8];
    const float* bv = (const float*)d_in[9];
    const float* Wo = (const float*)d_in[10];
    const float* bo = (const float*)d_in[11];

    float* out_x    = (float*)d_out;
    float* out_dist = (float*)d_out + (size_t)BB * SS * DD;

    void* pq; void* pk; void* pv; void* px; void* pbits;
    cudaGetSymbolAddress(&pq, g_q);
    cudaGetSymbolAddress(&pk, g_k);
    cudaGetSymbolAddress(&pv, g_v);
    cudaGetSymbolAddress(&px, g_x);
    cudaGetSymbolAddress(&pbits, g_mbits);

    cudaFuncSetAttribute(attn_fused, cudaFuncAttributeMaxDynamicSharedMemorySize, ATTN_SMEM_B);

    pack_mask_kernel<<<(BB * SS * (SS/32)) / 256, 256>>>(mask, (unsigned*)pbits);

    dim3 gqkv(DD / 128, (BB * SS) / 128, 3);                // (4, 64, 3)
    qkv_proj<<<gqkv, 256>>>(Q, K, V, Wq, bq, Wk, bk, Wv, bv,
                            (float*)pq, (float*)pk, (float*)pv);

    dim3 gattn(SS / 64, BH);                                // (32, 32)
    attn_fused<<<gattn, 256, ATTN_SMEM_B>>>(out_dist);

    dim3 gproj(DD / 128, (BB * SS) / 128);                  // (4, 64)
    proj_mma<<<gproj, 256>>>((const float*)px, Wo, bo, out_x, 0);
}

// round 15
// speedup vs baseline: 1.8978x; 1.1165x over previous
#include <cuda_runtime.h>
#include <cuda_fp16.h>
#include <cstdint>
#include <math.h>

#define BB 4
#define SS 2048
#define DD 512
#define HH 8
#define HD 64
#define BH (BB*HH)

__device__ float    g_q[BH * SS * HD];
__device__ float    g_k[BH * SS * HD];
__device__ float    g_v[BH * SS * HD];
__device__ float    g_x[BB * SS * DD];
__device__ unsigned g_mbits[BB * SS * (SS/32)];
__device__ __half   g_p[(size_t)BH * SS * SS];   // unnormalized exp(P), fp16 (268MB)

// ---------------------------------------------------------------------------
__device__ __forceinline__ void mma_f16(float c[4], const unsigned a[4], const unsigned b[2]) {
    asm volatile(
        "mma.sync.aligned.m16n8k16.row.col.f32.f16.f16.f32 "
        "{%0,%1,%2,%3},{%4,%5,%6,%7},{%8,%9},{%0,%1,%2,%3};"
        : "+f"(c[0]), "+f"(c[1]), "+f"(c[2]), "+f"(c[3])
        : "r"(a[0]), "r"(a[1]), "r"(a[2]), "r"(a[3]), "r"(b[0]), "r"(b[1]));
}
__device__ __forceinline__ void ldmx4t(unsigned r[4], const __half* p) {
    unsigned a = (unsigned)__cvta_generic_to_shared(p);
    asm volatile("ldmatrix.sync.aligned.m8n8.x4.trans.shared.b16 {%0,%1,%2,%3}, [%4];"
        : "=r"(r[0]), "=r"(r[1]), "=r"(r[2]), "=r"(r[3]) : "r"(a));
}
__device__ __forceinline__ unsigned h2u(__half2 h) { return *(unsigned*)&h; }
__device__ __forceinline__ float ex2f(float x) {
    float r; asm("ex2.approx.ftz.f32 %0, %1;" : "=f"(r) : "f"(x)); return r;
}
#define CEXP 0.18033688011112042f   // 0.125 * log2(e)

// ---------------------------------------------------------------------------
__global__ __launch_bounds__(256) void pack_mask_kernel(
    const int* __restrict__ mask, unsigned* __restrict__ bits)
{
    int w = blockIdx.x * 256 + threadIdx.x;
    const int4* p = (const int4*)(mask + (size_t)w * 32);
    unsigned v = 0;
    #pragma unroll
    for (int i = 0; i < 8; i++) {
        int4 q = p[i];
        v |= (unsigned)(q.x != 0) << (i * 4 + 0);
        v |= (unsigned)(q.y != 0) << (i * 4 + 1);
        v |= (unsigned)(q.z != 0) << (i * 4 + 2);
        v |= (unsigned)(q.w != 0) << (i * 4 + 3);
    }
    bits[w] = v;
}

// ---------------------------------------------------------------------------
// Projection GEMM body (R13 fp16 HMMA, unchanged): C = X @ W^T + bias.
// ---------------------------------------------------------------------------
__device__ __forceinline__ void proj_body(
    const float* __restrict__ X, const float* __restrict__ W,
    const float* __restrict__ bias, float* __restrict__ out, int scatter,
    int m0, int n0)
{
    __shared__ __align__(16) __half As[128 * 72];
    __shared__ __align__(16) __half Bs[128 * 72];

    const int t = threadIdx.x;
    const int warp = t >> 5, lane = t & 31;
    const int wm = warp >> 2, wn = warp & 3;
    const int g = lane >> 2, tig = lane & 3;

    float acc[4][4][4] = {};

    for (int k0 = 0; k0 < DD; k0 += 64) {
        #pragma unroll
        for (int i = 0; i < 8; i++) {
            int id = i * 256 + t;
            int r = id >> 4, c4 = (id & 15) * 4;
            float4 xv = *(const float4*)&X[(size_t)(m0 + r) * DD + k0 + c4];
            *(uint2*)&As[r * 72 + c4] = make_uint2(
                h2u(__floats2half2_rn(xv.x, xv.y)), h2u(__floats2half2_rn(xv.z, xv.w)));
            float4 wv = *(const float4*)&W[(size_t)(n0 + r) * DD + k0 + c4];
            *(uint2*)&Bs[r * 72 + c4] = make_uint2(
                h2u(__floats2half2_rn(wv.x, wv.y)), h2u(__floats2half2_rn(wv.z, wv.w)));
        }
        __syncthreads();

        #pragma unroll
        for (int kk = 0; kk < 64; kk += 16) {
            unsigned af[4][4], bf[4][2];
            #pragma unroll
            for (int mt = 0; mt < 4; mt++) {
                int mrow = wm * 64 + mt * 16;
                af[mt][0] = *(unsigned*)&As[(mrow + g) * 72 + kk + 2 * tig];
                af[mt][1] = *(unsigned*)&As[(mrow + g + 8) * 72 + kk + 2 * tig];
                af[mt][2] = *(unsigned*)&As[(mrow + g) * 72 + kk + 2 * tig + 8];
                af[mt][3] = *(unsigned*)&As[(mrow + g + 8) * 72 + kk + 2 * tig + 8];
            }
            #pragma unroll
            for (int nt = 0; nt < 4; nt++) {
                int ncol = wn * 32 + nt * 8 + g;
                bf[nt][0] = *(unsigned*)&Bs[ncol * 72 + kk + 2 * tig];
                bf[nt][1] = *(unsigned*)&Bs[ncol * 72 + kk + 2 * tig + 8];
            }
            #pragma unroll
            for (int mt = 0; mt < 4; mt++)
                #pragma unroll
                for (int nt = 0; nt < 4; nt++)
                    mma_f16(acc[mt][nt], af[mt], bf[nt]);
        }
        __syncthreads();
    }

    #pragma unroll
    for (int nt = 0; nt < 4; nt++) {
        const int col = n0 + wn * 32 + nt * 8 + 2 * tig;
        const float b0v = bias[col], b1v = bias[col + 1];
        #pragma unroll
        for (int mt = 0; mt < 4; mt++) {
            #pragma unroll
            for (int half = 0; half < 2; half++) {
                int m = m0 + wm * 64 + mt * 16 + g + half * 8;
                float2 v;
                v.x = acc[mt][nt][half * 2 + 0] + b0v;
                v.y = acc[mt][nt][half * 2 + 1] + b1v;
                if (scatter) {
                    int b = m >> 11, s = m & (SS - 1);
                    int h = col >> 6, hd = col & (HD - 1);
                    *(float2*)&out[(((size_t)(b * HH + h)) * SS + s) * HD + hd] = v;
                } else {
                    *(float2*)&out[(size_t)m * DD + col] = v;
                }
            }
        }
    }
}

__global__ __launch_bounds__(256) void qkv_proj(
    const float* __restrict__ Q, const float* __restrict__ K, const float* __restrict__ V,
    const float* __restrict__ Wq, const float* __restrict__ bq,
    const float* __restrict__ Wk, const float* __restrict__ bk,
    const float* __restrict__ Wv, const float* __restrict__ bv,
    float* __restrict__ oq, float* __restrict__ ok, float* __restrict__ ov)
{
    const float *X, *W, *bias; float* out;
    if (blockIdx.z == 0)      { X = Q; W = Wq; bias = bq; out = oq; }
    else if (blockIdx.z == 1) { X = K; W = Wk; bias = bk; out = ok; }
    else                      { X = V; W = Wv; bias = bv; out = ov; }
    proj_body(X, W, bias, out, 1, blockIdx.y * 128, blockIdx.x * 128);
}

__global__ __launch_bounds__(256) void proj_mma(
    const float* __restrict__ X, const float* __restrict__ W,
    const float* __restrict__ bias, float* __restrict__ out, int scatter)
{
    proj_body(X, W, bias, out, scatter, blockIdx.y * 128, blockIdx.x * 128);
}

// ---------------------------------------------------------------------------
// Fused attention, fp16 HMMA, P staged through g_p (no recompute).
// Phase A: S MMA -> exp -> rowsums + write fp16 P to g_p (coalesced, 16 h/thr).
// Phase B: read g_p -> normalize -> dist (float4) + PV MMA; y *= inv at end.
// 64x64 tiles, 3 blocks/SM.
// ---------------------------------------------------------------------------
#define HQS 0
#define HKS 4608
#define HVS 9216
#define HPS 13824
#define HRS 18432
#define ATTN_SMEM_B ((18432 + 128) * 2)   // 37,120 B

__global__ __launch_bounds__(256, 3) void attn_fused(float* __restrict__ dist)
{
    extern __shared__ __half hsm[];
    __half* Qs = hsm + HQS;
    __half* Ks = hsm + HKS;
    __half* Vs = hsm + HVS;
    __half* Ps = hsm + HPS;
    float* rowsum = (float*)(hsm + HRS);

    const int t = threadIdx.x;
    const int warp = t >> 5, lane = t & 31;
    const int wm = warp >> 2, wn = warp & 3;   // 2m x 4n, warp tile 32x16
    const int g = lane >> 2, tig = lane & 3;
    const int bh = blockIdx.y, b = bh >> 3, h = bh & 7;
    const int m0 = blockIdx.x * 64;

    const float* q = g_q + (size_t)bh * SS * HD;
    const float* k = g_k + (size_t)bh * SS * HD;
    const float* v = g_v + (size_t)bh * SS * HD;

    // load Q tile (64x64 half, resident)
    #pragma unroll
    for (int i = 0; i < 4; i++) {
        int id = i * 256 + t;
        int r = id >> 4, c4 = (id & 15) * 4;
        float4 qv = *(const float4*)&q[(size_t)(m0 + r) * HD + c4];
        *(uint2*)&Qs[r * 72 + c4] = make_uint2(
            h2u(__floats2half2_rn(qv.x, qv.y)), h2u(__floats2half2_rn(qv.z, qv.w)));
    }
    if (t < 64) rowsum[t] = 0.0f;

    float rs[2][2] = {};
    const int pr = t >> 2, pc = (t & 3) * 16;   // each thread: 16 halfs of one row

    // ======== Phase A: S MMA + exp + rowsums + stage P to g_p ========
    for (int it = 0; it < 32; it++) {
        const int n0 = it * 64;
        __syncthreads();
        #pragma unroll
        for (int i = 0; i < 4; i++) {
            int id = i * 256 + t;
            int r = id >> 4, c4 = (id & 15) * 4;
            float4 kv = *(const float4*)&k[(size_t)(n0 + r) * HD + c4];
            *(uint2*)&Ks[r * 72 + c4] = make_uint2(
                h2u(__floats2half2_rn(kv.x, kv.y)), h2u(__floats2half2_rn(kv.z, kv.w)));
        }
        __syncthreads();

        float acc[2][2][4] = {};
        #pragma unroll
        for (int kk = 0; kk < 64; kk += 16) {
            unsigned af[2][4], bf[2][2];
            #pragma unroll
            for (int mt = 0; mt < 2; mt++) {
                int mrow = wm * 32 + mt * 16;
                af[mt][0] = *(unsigned*)&Qs[(mrow + g) * 72 + kk + 2 * tig];
                af[mt][1] = *(unsigned*)&Qs[(mrow + g + 8) * 72 + kk + 2 * tig];
                af[mt][2] = *(unsigned*)&Qs[(mrow + g) * 72 + kk + 2 * tig + 8];
                af[mt][3] = *(unsigned*)&Qs[(mrow + g + 8) * 72 + kk + 2 * tig + 8];
            }
            #pragma unroll
            for (int nt = 0; nt < 2; nt++) {
                int ncol = wn * 16 + nt * 8 + g;
                bf[nt][0] = *(unsigned*)&Ks[ncol * 72 + kk + 2 * tig];
                bf[nt][1] = *(unsigned*)&Ks[ncol * 72 + kk + 2 * tig + 8];
            }
            #pragma unroll
            for (int mt = 0; mt < 2; mt++)
                #pragma unroll
                for (int nt = 0; nt < 2; nt++)
                    mma_f16(acc[mt][nt], af[mt], bf[nt]);
        }

        // exp + rowsums + deposit fp16 P into Ps
        #pragma unroll
        for (int mt = 0; mt < 2; mt++) {
            #pragma unroll
            for (int half = 0; half < 2; half++) {
                int rowl = wm * 32 + mt * 16 + g + half * 8;
                int row = m0 + rowl;
                unsigned mb = g_mbits[((size_t)b * SS + row) * (SS/32) + (n0 >> 5) + (wn >> 1)];
                int bitbase = (wn & 1) * 16;
                #pragma unroll
                for (int nt = 0; nt < 2; nt++) {
                    int nloc = nt * 8 + 2 * tig;
                    float e0 = ((mb >> (bitbase + nloc)) & 1u) ? 0.0f : ex2f(acc[mt][nt][half*2+0] * CEXP);
                    float e1 = ((mb >> (bitbase + nloc + 1)) & 1u) ? 0.0f : ex2f(acc[mt][nt][half*2+1] * CEXP);
                    rs[mt][half] += e0 + e1;
                    *(unsigned*)&Ps[rowl * 72 + wn * 16 + nloc] = h2u(__floats2half2_rn(e0, e1));
                }
            }
        }
        __syncthreads();

        // coalesced Ps -> g_p: 16 halfs per thread = 2 x uint4
        {
            uint4 p0 = *(uint4*)&Ps[pr * 72 + pc];
            uint4 p1 = *(uint4*)&Ps[pr * 72 + pc + 8];
            __half* gp = &g_p[((size_t)bh * SS + m0 + pr) * SS + n0 + pc];
            *(uint4*)gp = p0;
            *(uint4*)(gp + 8) = p1;
        }
    }

    // reduce row sums, invert
    #pragma unroll
    for (int mt = 0; mt < 2; mt++)
        #pragma unroll
        for (int half = 0; half < 2; half++) {
            float s = rs[mt][half];
            s += __shfl_xor_sync(0xffffffffu, s, 1);
            s += __shfl_xor_sync(0xffffffffu, s, 2);
            if (tig == 0)
                atomicAdd(&rowsum[wm * 32 + mt * 16 + g + half * 8], s);
        }
    __syncthreads();
    if (t < 64) rowsum[t] = 1.0f / rowsum[t];

    // ======== Phase B: read g_p, normalize->dist, PV MMA ========
    float y[2][2][4] = {};
    const size_t dbase = (size_t)bh * SS * SS;

    for (int it = 0; it < 32; it++) {
        const int n0 = it * 64;
        __syncthreads();    // Ps/Vs consumed from prev iter; inv visible on it==0

        // V tile
        #pragma unroll
        for (int i = 0; i < 4; i++) {
            int id = i * 256 + t;
            int r = id >> 4, c4 = (id & 15) * 4;
            float4 vv = *(const float4*)&v[(size_t)(n0 + r) * HD + c4];
            *(uint2*)&Vs[r * 72 + c4] = make_uint2(
                h2u(__floats2half2_rn(vv.x, vv.y)), h2u(__floats2half2_rn(vv.z, vv.w)));
        }

        // g_p tile -> Ps + normalized dist (float4 coalesced); 16 halfs/thread
        {
            const __half* gp = &g_p[((size_t)bh * SS + m0 + pr) * SS + n0 + pc];
            uint4 p0 = *(const uint4*)gp;
            uint4 p1 = *(const uint4*)(gp + 8);
            *(uint4*)&Ps[pr * 72 + pc] = p0;
            *(uint4*)&Ps[pr * 72 + pc + 8] = p1;
            float inv = rowsum[pr];
            float* dp = &dist[dbase + (size_t)(m0 + pr) * SS + n0 + pc];
            const __half* h0 = (const __half*)&p0;
            const __half* h1 = (const __half*)&p1;
            #pragma unroll
            for (int j = 0; j < 2; j++) {
                float4 o;
                o.x = __half2float(h0[j * 4 + 0]) * inv;
                o.y = __half2float(h0[j * 4 + 1]) * inv;
                o.z = __half2float(h0[j * 4 + 2]) * inv;
                o.w = __half2float(h0[j * 4 + 3]) * inv;
                *(float4*)(dp + j * 4) = o;
            }
            #pragma unroll
            for (int j = 0; j < 2; j++) {
                float4 o;
                o.x = __half2float(h1[j * 4 + 0]) * inv;
                o.y = __half2float(h1[j * 4 + 1]) * inv;
                o.z = __half2float(h1[j * 4 + 2]) * inv;
                o.w = __half2float(h1[j * 4 + 3]) * inv;
                *(float4*)(dp + 8 + j * 4) = o;
            }
        }
        __syncthreads();

        // PV: y += P(unnorm)[64x64] @ V[64x64]
        #pragma unroll
        for (int kk = 0; kk < 64; kk += 16) {
            unsigned af[2][4], bv[4];
            #pragma unroll
            for (int mt = 0; mt < 2; mt++) {
                int mrow = wm * 32 + mt * 16;
                af[mt][0] = *(unsigned*)&Ps[(mrow + g) * 72 + kk + 2 * tig];
                af[mt][1] = *(unsigned*)&Ps[(mrow + g + 8) * 72 + kk + 2 * tig];
                af[mt][2] = *(unsigned*)&Ps[(mrow + g) * 72 + kk + 2 * tig + 8];
                af[mt][3] = *(unsigned*)&Ps[(mrow + g + 8) * 72 + kk + 2 * tig + 8];
            }
            ldmx4t(bv, &Vs[(kk + (lane & 15)) * 72 + wn * 16 + (lane >> 4) * 8]);
            #pragma unroll
            for (int mt = 0; mt < 2; mt++) {
                mma_f16(y[mt][0], af[mt], bv + 0);
                mma_f16(y[mt][1], af[mt], bv + 2);
            }
        }
    }

    // write x = y * inv (P was unnormalized)
    #pragma unroll
    for (int mt = 0; mt < 2; mt++) {
        #pragma unroll
        for (int nt = 0; nt < 2; nt++) {
            #pragma unroll
            for (int half = 0; half < 2; half++) {
                int rowl = wm * 32 + mt * 16 + g + half * 8;
                int row = m0 + rowl;
                int col = wn * 16 + nt * 8 + 2 * tig;
                float inv = rowsum[rowl];
                float2 o;
                o.x = y[mt][nt][half * 2 + 0] * inv;
                o.y = y[mt][nt][half * 2 + 1] * inv;
                *(float2*)&g_x[((size_t)(b * SS + row)) * DD + h * HD + col] = o;
            }
        }
    }
}

// ---------------------------------------------------------------------------
extern "C" void kernel_launch(void* const* d_in, const int* in_sizes, int n_in,
                              void* d_out, int out_size)
{
    const float* Q  = (const float*)d_in[0];
    const float* K  = (const float*)d_in[1];
    const float* V  = (const float*)d_in[2];
    const int*   mask = (const int*)d_in[3];
    const float* Wq = (const float*)d_in[4];
    const float* bq = (const float*)d_in[5];
    const float* Wk = (const float*)d_in[6];
    const float* bk = (const float*)d_in[7];
    const float* Wv = (const float*)d_in[8];
    const float* bv = (const float*)d_in[9];
    const float* Wo = (const float*)d_in[10];
    const float* bo = (const float*)d_in[11];

    float* out_x    = (float*)d_out;
    float* out_dist = (float*)d_out + (size_t)BB * SS * DD;

    void* pq; void* pk; void* pv; void* px; void* pbits;
    cudaGetSymbolAddress(&pq, g_q);
    cudaGetSymbolAddress(&pk, g_k);
    cudaGetSymbolAddress(&pv, g_v);
    cudaGetSymbolAddress(&px, g_x);
    cudaGetSymbolAddress(&pbits, g_mbits);

    cudaFuncSetAttribute(attn_fused, cudaFuncAttributeMaxDynamicSharedMemorySize, ATTN_SMEM_B);

    pack_mask_kernel<<<(BB * SS * (SS/32)) / 256, 256>>>(mask, (unsigned*)pbits);

    dim3 gqkv(DD / 128, (BB * SS) / 128, 3);                // (4, 64, 3)
    qkv_proj<<<gqkv, 256>>>(Q, K, V, Wq, bq, Wk, bk, Wv, bv,
                            (float*)pq, (float*)pk, (float*)pv);

    dim3 gattn(SS / 64, BH);                                // (32, 32)
    attn_fused<<<gattn, 256, ATTN_SMEM_B>>>(out_dist);

    dim3 gproj(DD / 128, (BB * SS) / 128);                  // (4, 64)
    proj_mma<<<gproj, 256>>>((const float*)px, Wo, bo, out_x, 0);
}

// round 16
// speedup vs baseline: 1.9161x; 1.0096x over previous
#include <cuda_runtime.h>
#include <cuda_fp16.h>
#include <cstdint>
#include <math.h>

#define BB 4
#define SS 2048
#define DD 512
#define HH 8
#define HD 64
#define BH (BB*HH)

__device__ float    g_q[BH * SS * HD];
__device__ float    g_k[BH * SS * HD];
__device__ float    g_v[BH * SS * HD];
__device__ float    g_x[BB * SS * DD];
__device__ unsigned g_mbits[BB * SS * (SS/32)];
__device__ __half   g_p[(size_t)BH * SS * SS];   // unnormalized exp(P), fp16

// ---------------------------------------------------------------------------
__device__ __forceinline__ void mma_f16(float c[4], const unsigned a[4], const unsigned b[2]) {
    asm volatile(
        "mma.sync.aligned.m16n8k16.row.col.f32.f16.f16.f32 "
        "{%0,%1,%2,%3},{%4,%5,%6,%7},{%8,%9},{%0,%1,%2,%3};"
        : "+f"(c[0]), "+f"(c[1]), "+f"(c[2]), "+f"(c[3])
        : "r"(a[0]), "r"(a[1]), "r"(a[2]), "r"(a[3]), "r"(b[0]), "r"(b[1]));
}
// non-transposed ldmatrix x4
__device__ __forceinline__ void ldmx4(unsigned r[4], const __half* p) {
    unsigned a = (unsigned)__cvta_generic_to_shared(p);
    asm volatile("ldmatrix.sync.aligned.m8n8.x4.shared.b16 {%0,%1,%2,%3}, [%4];"
        : "=r"(r[0]), "=r"(r[1]), "=r"(r[2]), "=r"(r[3]) : "r"(a));
}
__device__ __forceinline__ void ldmx4t(unsigned r[4], const __half* p) {
    unsigned a = (unsigned)__cvta_generic_to_shared(p);
    asm volatile("ldmatrix.sync.aligned.m8n8.x4.trans.shared.b16 {%0,%1,%2,%3}, [%4];"
        : "=r"(r[0]), "=r"(r[1]), "=r"(r[2]), "=r"(r[3]) : "r"(a));
}
__device__ __forceinline__ unsigned h2u(__half2 h) { return *(unsigned*)&h; }
__device__ __forceinline__ float ex2f(float x) {
    float r; asm("ex2.approx.ftz.f32 %0, %1;" : "=f"(r) : "f"(x)); return r;
}
#define CEXP 0.18033688011112042f   // 0.125 * log2(e)

// A-type fragment address (16x16 fragment at (mrow, kk), stride 72 halfs)
#define AFRAG_ADDR(base, mrow, kk, lane) \
    (&(base)[((mrow) + ((lane) & 15)) * 72 + (kk) + (((lane) >> 4) << 3)])
// B-type fragment address (16 n-rows at (ncol0, kk)): M0=n0-7@kk, M1=n0-7@kk+8, M2=n8-15@kk, M3=n8-15@kk+8
#define BFRAG_ADDR(base, ncol0, kk, lane) \
    (&(base)[((ncol0) + (((lane) >> 4) << 3) + ((lane) & 7)) * 72 + (kk) + ((((lane) >> 3) & 1) << 3)])

// ---------------------------------------------------------------------------
__global__ __launch_bounds__(256) void pack_mask_kernel(
    const int* __restrict__ mask, unsigned* __restrict__ bits)
{
    int w = blockIdx.x * 256 + threadIdx.x;
    const int4* p = (const int4*)(mask + (size_t)w * 32);
    unsigned v = 0;
    #pragma unroll
    for (int i = 0; i < 8; i++) {
        int4 q = p[i];
        v |= (unsigned)(q.x != 0) << (i * 4 + 0);
        v |= (unsigned)(q.y != 0) << (i * 4 + 1);
        v |= (unsigned)(q.z != 0) << (i * 4 + 2);
        v |= (unsigned)(q.w != 0) << (i * 4 + 3);
    }
    bits[w] = v;
}

// ---------------------------------------------------------------------------
// Projection GEMM body, fp16 HMMA + LDSM fragments: C = X @ W^T + bias.
// ---------------------------------------------------------------------------
__device__ __forceinline__ void proj_body(
    const float* __restrict__ X, const float* __restrict__ W,
    const float* __restrict__ bias, float* __restrict__ out, int scatter,
    int m0, int n0)
{
    __shared__ __align__(16) __half As[128 * 72];
    __shared__ __align__(16) __half Bs[128 * 72];

    const int t = threadIdx.x;
    const int warp = t >> 5, lane = t & 31;
    const int wm = warp >> 2, wn = warp & 3;
    const int g = lane >> 2, tig = lane & 3;

    float acc[4][4][4] = {};

    for (int k0 = 0; k0 < DD; k0 += 64) {
        #pragma unroll
        for (int i = 0; i < 8; i++) {
            int id = i * 256 + t;
            int r = id >> 4, c4 = (id & 15) * 4;
            float4 xv = *(const float4*)&X[(size_t)(m0 + r) * DD + k0 + c4];
            *(uint2*)&As[r * 72 + c4] = make_uint2(
                h2u(__floats2half2_rn(xv.x, xv.y)), h2u(__floats2half2_rn(xv.z, xv.w)));
            float4 wv = *(const float4*)&W[(size_t)(n0 + r) * DD + k0 + c4];
            *(uint2*)&Bs[r * 72 + c4] = make_uint2(
                h2u(__floats2half2_rn(wv.x, wv.y)), h2u(__floats2half2_rn(wv.z, wv.w)));
        }
        __syncthreads();

        #pragma unroll
        for (int kk = 0; kk < 64; kk += 16) {
            unsigned af[4][4], bf[4][2];
            #pragma unroll
            for (int mt = 0; mt < 4; mt++)
                ldmx4(af[mt], AFRAG_ADDR(As, wm * 64 + mt * 16, kk, lane));
            #pragma unroll
            for (int nt2 = 0; nt2 < 2; nt2++) {
                unsigned bq[4];
                ldmx4(bq, BFRAG_ADDR(Bs, wn * 32 + nt2 * 16, kk, lane));
                bf[nt2 * 2 + 0][0] = bq[0]; bf[nt2 * 2 + 0][1] = bq[1];
                bf[nt2 * 2 + 1][0] = bq[2]; bf[nt2 * 2 + 1][1] = bq[3];
            }
            #pragma unroll
            for (int mt = 0; mt < 4; mt++)
                #pragma unroll
                for (int nt = 0; nt < 4; nt++)
                    mma_f16(acc[mt][nt], af[mt], bf[nt]);
        }
        __syncthreads();
    }

    #pragma unroll
    for (int nt = 0; nt < 4; nt++) {
        const int col = n0 + wn * 32 + nt * 8 + 2 * tig;
        const float b0v = bias[col], b1v = bias[col + 1];
        #pragma unroll
        for (int mt = 0; mt < 4; mt++) {
            #pragma unroll
            for (int half = 0; half < 2; half++) {
                int m = m0 + wm * 64 + mt * 16 + g + half * 8;
                float2 v;
                v.x = acc[mt][nt][half * 2 + 0] + b0v;
                v.y = acc[mt][nt][half * 2 + 1] + b1v;
                if (scatter) {
                    int b = m >> 11, s = m & (SS - 1);
                    int h = col >> 6, hd = col & (HD - 1);
                    *(float2*)&out[(((size_t)(b * HH + h)) * SS + s) * HD + hd] = v;
                } else {
                    *(float2*)&out[(size_t)m * DD + col] = v;
                }
            }
        }
    }
}

__global__ __launch_bounds__(256) void qkv_proj(
    const float* __restrict__ Q, const float* __restrict__ K, const float* __restrict__ V,
    const float* __restrict__ Wq, const float* __restrict__ bq,
    const float* __restrict__ Wk, const float* __restrict__ bk,
    const float* __restrict__ Wv, const float* __restrict__ bv,
    float* __restrict__ oq, float* __restrict__ ok, float* __restrict__ ov)
{
    const float *X, *W, *bias; float* out;
    if (blockIdx.z == 0)      { X = Q; W = Wq; bias = bq; out = oq; }
    else if (blockIdx.z == 1) { X = K; W = Wk; bias = bk; out = ok; }
    else                      { X = V; W = Wv; bias = bv; out = ov; }
    proj_body(X, W, bias, out, 1, blockIdx.y * 128, blockIdx.x * 128);
}

__global__ __launch_bounds__(256) void proj_mma(
    const float* __restrict__ X, const float* __restrict__ W,
    const float* __restrict__ bias, float* __restrict__ out, int scatter)
{
    proj_body(X, W, bias, out, scatter, blockIdx.y * 128, blockIdx.x * 128);
}

// ---------------------------------------------------------------------------
// Fused attention, fp16 HMMA + LDSM, P staged through g_p.
// ---------------------------------------------------------------------------
#define HQS 0
#define HKS 4608
#define HVS 9216
#define HPS 13824
#define HRS 18432
#define ATTN_SMEM_B ((18432 + 128) * 2)   // 37,120 B

__global__ __launch_bounds__(256, 3) void attn_fused(float* __restrict__ dist)
{
    extern __shared__ __half hsm[];
    __half* Qs = hsm + HQS;
    __half* Ks = hsm + HKS;
    __half* Vs = hsm + HVS;
    __half* Ps = hsm + HPS;
    float* rowsum = (float*)(hsm + HRS);

    const int t = threadIdx.x;
    const int warp = t >> 5, lane = t & 31;
    const int wm = warp >> 2, wn = warp & 3;   // 2m x 4n, warp tile 32x16
    const int g = lane >> 2, tig = lane & 3;
    const int bh = blockIdx.y, b = bh >> 3, h = bh & 7;
    const int m0 = blockIdx.x * 64;

    const float* q = g_q + (size_t)bh * SS * HD;
    const float* k = g_k + (size_t)bh * SS * HD;
    const float* v = g_v + (size_t)bh * SS * HD;

    // load Q tile (64x64 half, resident)
    #pragma unroll
    for (int i = 0; i < 4; i++) {
        int id = i * 256 + t;
        int r = id >> 4, c4 = (id & 15) * 4;
        float4 qv = *(const float4*)&q[(size_t)(m0 + r) * HD + c4];
        *(uint2*)&Qs[r * 72 + c4] = make_uint2(
            h2u(__floats2half2_rn(qv.x, qv.y)), h2u(__floats2half2_rn(qv.z, qv.w)));
    }
    if (t < 64) rowsum[t] = 0.0f;

    float rs[2][2] = {};
    const int pr = t >> 2, pc = (t & 3) * 16;

    // ======== Phase A: S MMA + exp + rowsums + stage P to g_p ========
    for (int it = 0; it < 32; it++) {
        const int n0 = it * 64;
        __syncthreads();
        #pragma unroll
        for (int i = 0; i < 4; i++) {
            int id = i * 256 + t;
            int r = id >> 4, c4 = (id & 15) * 4;
            float4 kv = *(const float4*)&k[(size_t)(n0 + r) * HD + c4];
            *(uint2*)&Ks[r * 72 + c4] = make_uint2(
                h2u(__floats2half2_rn(kv.x, kv.y)), h2u(__floats2half2_rn(kv.z, kv.w)));
        }
        __syncthreads();

        float acc[2][2][4] = {};
        #pragma unroll
        for (int kk = 0; kk < 64; kk += 16) {
            unsigned af[2][4], bf[2][2];
            #pragma unroll
            for (int mt = 0; mt < 2; mt++)
                ldmx4(af[mt], AFRAG_ADDR(Qs, wm * 32 + mt * 16, kk, lane));
            {
                unsigned bq2[4];
                ldmx4(bq2, BFRAG_ADDR(Ks, wn * 16, kk, lane));
                bf[0][0] = bq2[0]; bf[0][1] = bq2[1];
                bf[1][0] = bq2[2]; bf[1][1] = bq2[3];
            }
            #pragma unroll
            for (int mt = 0; mt < 2; mt++)
                #pragma unroll
                for (int nt = 0; nt < 2; nt++)
                    mma_f16(acc[mt][nt], af[mt], bf[nt]);
        }

        // exp + rowsums + deposit fp16 P into Ps
        #pragma unroll
        for (int mt = 0; mt < 2; mt++) {
            #pragma unroll
            for (int half = 0; half < 2; half++) {
                int rowl = wm * 32 + mt * 16 + g + half * 8;
                int row = m0 + rowl;
                unsigned mb = g_mbits[((size_t)b * SS + row) * (SS/32) + (n0 >> 5) + (wn >> 1)];
                int bitbase = (wn & 1) * 16;
                #pragma unroll
                for (int nt = 0; nt < 2; nt++) {
                    int nloc = nt * 8 + 2 * tig;
                    float e0 = ((mb >> (bitbase + nloc)) & 1u) ? 0.0f : ex2f(acc[mt][nt][half*2+0] * CEXP);
                    float e1 = ((mb >> (bitbase + nloc + 1)) & 1u) ? 0.0f : ex2f(acc[mt][nt][half*2+1] * CEXP);
                    rs[mt][half] += e0 + e1;
                    *(unsigned*)&Ps[rowl * 72 + wn * 16 + nloc] = h2u(__floats2half2_rn(e0, e1));
                }
            }
        }
        __syncthreads();

        // coalesced Ps -> g_p: 16 halfs per thread = 2 x uint4
        {
            uint4 p0 = *(uint4*)&Ps[pr * 72 + pc];
            uint4 p1 = *(uint4*)&Ps[pr * 72 + pc + 8];
            __half* gp = &g_p[((size_t)bh * SS + m0 + pr) * SS + n0 + pc];
            *(uint4*)gp = p0;
            *(uint4*)(gp + 8) = p1;
        }
    }

    // reduce row sums, invert
    #pragma unroll
    for (int mt = 0; mt < 2; mt++)
        #pragma unroll
        for (int half = 0; half < 2; half++) {
            float s = rs[mt][half];
            s += __shfl_xor_sync(0xffffffffu, s, 1);
            s += __shfl_xor_sync(0xffffffffu, s, 2);
            if (tig == 0)
                atomicAdd(&rowsum[wm * 32 + mt * 16 + g + half * 8], s);
        }
    __syncthreads();
    if (t < 64) rowsum[t] = 1.0f / rowsum[t];

    // ======== Phase B: read g_p, normalize->dist, PV MMA ========
    float y[2][2][4] = {};
    const size_t dbase = (size_t)bh * SS * SS;

    for (int it = 0; it < 32; it++) {
        const int n0 = it * 64;
        __syncthreads();

        // V tile
        #pragma unroll
        for (int i = 0; i < 4; i++) {
            int id = i * 256 + t;
            int r = id >> 4, c4 = (id & 15) * 4;
            float4 vv = *(const float4*)&v[(size_t)(n0 + r) * HD + c4];
            *(uint2*)&Vs[r * 72 + c4] = make_uint2(
                h2u(__floats2half2_rn(vv.x, vv.y)), h2u(__floats2half2_rn(vv.z, vv.w)));
        }

        // g_p tile -> Ps + normalized dist (float4 coalesced); 16 halfs/thread
        {
            const __half* gp = &g_p[((size_t)bh * SS + m0 + pr) * SS + n0 + pc];
            uint4 p0 = *(const uint4*)gp;
            uint4 p1 = *(const uint4*)(gp + 8);
            *(uint4*)&Ps[pr * 72 + pc] = p0;
            *(uint4*)&Ps[pr * 72 + pc + 8] = p1;
            float inv = rowsum[pr];
            float* dp = &dist[dbase + (size_t)(m0 + pr) * SS + n0 + pc];
            const __half* h0 = (const __half*)&p0;
            const __half* h1 = (const __half*)&p1;
            #pragma unroll
            for (int j = 0; j < 2; j++) {
                float4 o;
                o.x = __half2float(h0[j * 4 + 0]) * inv;
                o.y = __half2float(h0[j * 4 + 1]) * inv;
                o.z = __half2float(h0[j * 4 + 2]) * inv;
                o.w = __half2float(h0[j * 4 + 3]) * inv;
                *(float4*)(dp + j * 4) = o;
            }
            #pragma unroll
            for (int j = 0; j < 2; j++) {
                float4 o;
                o.x = __half2float(h1[j * 4 + 0]) * inv;
                o.y = __half2float(h1[j * 4 + 1]) * inv;
                o.z = __half2float(h1[j * 4 + 2]) * inv;
                o.w = __half2float(h1[j * 4 + 3]) * inv;
                *(float4*)(dp + 8 + j * 4) = o;
            }
        }
        __syncthreads();

        // PV: y += P(unnorm)[64x64] @ V[64x64]
        #pragma unroll
        for (int kk = 0; kk < 64; kk += 16) {
            unsigned af[2][4], bv[4];
            #pragma unroll
            for (int mt = 0; mt < 2; mt++)
                ldmx4(af[mt], AFRAG_ADDR(Ps, wm * 32 + mt * 16, kk, lane));
            ldmx4t(bv, &Vs[(kk + (lane & 15)) * 72 + wn * 16 + (lane >> 4) * 8]);
            #pragma unroll
            for (int mt = 0; mt < 2; mt++) {
                mma_f16(y[mt][0], af[mt], bv + 0);
                mma_f16(y[mt][1], af[mt], bv + 2);
            }
        }
    }

    // write x = y * inv (P was unnormalized)
    #pragma unroll
    for (int mt = 0; mt < 2; mt++) {
        #pragma unroll
        for (int nt = 0; nt < 2; nt++) {
            #pragma unroll
            for (int half = 0; half < 2; half++) {
                int rowl = wm * 32 + mt * 16 + g + half * 8;
                int row = m0 + rowl;
                int col = wn * 16 + nt * 8 + 2 * tig;
                float inv = rowsum[rowl];
                float2 o;
                o.x = y[mt][nt][half * 2 + 0] * inv;
                o.y = y[mt][nt][half * 2 + 1] * inv;
                *(float2*)&g_x[((size_t)(b * SS + row)) * DD + h * HD + col] = o;
            }
        }
    }
}

// ---------------------------------------------------------------------------
extern "C" void kernel_launch(void* const* d_in, const int* in_sizes, int n_in,
                              void* d_out, int out_size)
{
    const float* Q  = (const float*)d_in[0];
    const float* K  = (const float*)d_in[1];
    const float* V  = (const float*)d_in[2];
    const int*   mask = (const int*)d_in[3];
    const float* Wq = (const float*)d_in[4];
    const float* bq = (const float*)d_in[5];
    const float* Wk = (const float*)d_in[6];
    const float* bk = (const float*)d_in[7];
    const float* Wv = (const float*)d_in[8];
    const float* bv = (const float*)d_in[9];
    const float* Wo = (const float*)d_in[10];
    const float* bo = (const float*)d_in[11];

    float* out_x    = (float*)d_out;
    float* out_dist = (float*)d_out + (size_t)BB * SS * DD;

    void* pq; void* pk; void* pv; void* px; void* pbits;
    cudaGetSymbolAddress(&pq, g_q);
    cudaGetSymbolAddress(&pk, g_k);
    cudaGetSymbolAddress(&pv, g_v);
    cudaGetSymbolAddress(&px, g_x);
    cudaGetSymbolAddress(&pbits, g_mbits);

    cudaFuncSetAttribute(attn_fused, cudaFuncAttributeMaxDynamicSharedMemorySize, ATTN_SMEM_B);

    pack_mask_kernel<<<(BB * SS * (SS/32)) / 256, 256>>>(mask, (unsigned*)pbits);

    dim3 gqkv(DD / 128, (BB * SS) / 128, 3);                // (4, 64, 3)
    qkv_proj<<<gqkv, 256>>>(Q, K, V, Wq, bq, Wk, bk, Wv, bv,
                            (float*)pq, (float*)pk, (float*)pv);

    dim3 gattn(SS / 64, BH);                                // (32, 32)
    attn_fused<<<gattn, 256, ATTN_SMEM_B>>>(out_dist);

    dim3 gproj(DD / 128, (BB * SS) / 128);                  // (4, 64)
    proj_mma<<<gproj, 256>>>((const float*)px, Wo, bo, out_x, 0);
}

// round 17
// speedup vs baseline: 2.1695x; 1.1323x over previous
#include <cuda_runtime.h>
#include <cuda_fp16.h>
#include <cstdint>
#include <math.h>

#define BB 4
#define SS 2048
#define DD 512
#define HH 8
#define HD 64
#define BH (BB*HH)

__device__ __half   g_q[BH * SS * HD];           // fp16 projected q/k/v
__device__ __half   g_k[BH * SS * HD];
__device__ __half   g_v[BH * SS * HD];
__device__ __half   g_x[BB * SS * DD];           // fp16 attention output
__device__ unsigned g_mbits[BB * SS * (SS/32)];
__device__ __half   g_p[(size_t)BH * SS * SS];   // unnormalized exp(P), fp16

// ---------------------------------------------------------------------------
__device__ __forceinline__ void mma_f16(float c[4], const unsigned a[4], const unsigned b[2]) {
    asm volatile(
        "mma.sync.aligned.m16n8k16.row.col.f32.f16.f16.f32 "
        "{%0,%1,%2,%3},{%4,%5,%6,%7},{%8,%9},{%0,%1,%2,%3};"
        : "+f"(c[0]), "+f"(c[1]), "+f"(c[2]), "+f"(c[3])
        : "r"(a[0]), "r"(a[1]), "r"(a[2]), "r"(a[3]), "r"(b[0]), "r"(b[1]));
}
__device__ __forceinline__ void ldmx4(unsigned r[4], const __half* p) {
    unsigned a = (unsigned)__cvta_generic_to_shared(p);
    asm volatile("ldmatrix.sync.aligned.m8n8.x4.shared.b16 {%0,%1,%2,%3}, [%4];"
        : "=r"(r[0]), "=r"(r[1]), "=r"(r[2]), "=r"(r[3]) : "r"(a));
}
__device__ __forceinline__ void ldmx4t(unsigned r[4], const __half* p) {
    unsigned a = (unsigned)__cvta_generic_to_shared(p);
    asm volatile("ldmatrix.sync.aligned.m8n8.x4.trans.shared.b16 {%0,%1,%2,%3}, [%4];"
        : "=r"(r[0]), "=r"(r[1]), "=r"(r[2]), "=r"(r[3]) : "r"(a));
}
__device__ __forceinline__ unsigned h2u(__half2 h) { return *(unsigned*)&h; }
__device__ __forceinline__ float ex2f(float x) {
    float r; asm("ex2.approx.ftz.f32 %0, %1;" : "=f"(r) : "f"(x)); return r;
}
__device__ __forceinline__ void cp16(void* dst_smem, const void* src_gmem) {
    unsigned d = (unsigned)__cvta_generic_to_shared(dst_smem);
    asm volatile("cp.async.cg.shared.global [%0], [%1], 16;" :: "r"(d), "l"(src_gmem));
}
#define CP_COMMIT()  asm volatile("cp.async.commit_group;")
#define CP_WAIT0()   asm volatile("cp.async.wait_group 0;")
#define CEXP 0.18033688011112042f   // 0.125 * log2(e)

#define AFRAG_ADDR(base, mrow, kk, lane) \
    (&(base)[((mrow) + ((lane) & 15)) * 72 + (kk) + (((lane) >> 4) << 3)])
#define BFRAG_ADDR(base, ncol0, kk, lane) \
    (&(base)[((ncol0) + (((lane) >> 4) << 3) + ((lane) & 7)) * 72 + (kk) + ((((lane) >> 3) & 1) << 3)])

// ---------------------------------------------------------------------------
__global__ __launch_bounds__(256) void pack_mask_kernel(
    const int* __restrict__ mask, unsigned* __restrict__ bits)
{
    int w = blockIdx.x * 256 + threadIdx.x;
    const int4* p = (const int4*)(mask + (size_t)w * 32);
    unsigned v = 0;
    #pragma unroll
    for (int i = 0; i < 8; i++) {
        int4 q = p[i];
        v |= (unsigned)(q.x != 0) << (i * 4 + 0);
        v |= (unsigned)(q.y != 0) << (i * 4 + 1);
        v |= (unsigned)(q.z != 0) << (i * 4 + 2);
        v |= (unsigned)(q.w != 0) << (i * 4 + 3);
    }
    bits[w] = v;
}

// ---------------------------------------------------------------------------
// QKV projections: fp32 in -> fp16 out (scattered [b,h,s,hd]).
// Block 128x128, 8 warps (2m x 4n), fp16 HMMA + LDSM.
// ---------------------------------------------------------------------------
__global__ __launch_bounds__(256) void qkv_proj(
    const float* __restrict__ Q, const float* __restrict__ K, const float* __restrict__ V,
    const float* __restrict__ Wq, const float* __restrict__ bq,
    const float* __restrict__ Wk, const float* __restrict__ bk,
    const float* __restrict__ Wv, const float* __restrict__ bv,
    __half* __restrict__ oq, __half* __restrict__ ok, __half* __restrict__ ov)
{
    const float *X, *W, *bias; __half* out;
    if (blockIdx.z == 0)      { X = Q; W = Wq; bias = bq; out = oq; }
    else if (blockIdx.z == 1) { X = K; W = Wk; bias = bk; out = ok; }
    else                      { X = V; W = Wv; bias = bv; out = ov; }
    const int m0 = blockIdx.y * 128, n0 = blockIdx.x * 128;

    __shared__ __align__(16) __half As[128 * 72];
    __shared__ __align__(16) __half Bs[128 * 72];

    const int t = threadIdx.x;
    const int warp = t >> 5, lane = t & 31;
    const int wm = warp >> 2, wn = warp & 3;
    const int g = lane >> 2, tig = lane & 3;

    float acc[4][4][4] = {};

    for (int k0 = 0; k0 < DD; k0 += 64) {
        #pragma unroll
        for (int i = 0; i < 8; i++) {
            int id = i * 256 + t;
            int r = id >> 4, c4 = (id & 15) * 4;
            float4 xv = *(const float4*)&X[(size_t)(m0 + r) * DD + k0 + c4];
            *(uint2*)&As[r * 72 + c4] = make_uint2(
                h2u(__floats2half2_rn(xv.x, xv.y)), h2u(__floats2half2_rn(xv.z, xv.w)));
            float4 wv = *(const float4*)&W[(size_t)(n0 + r) * DD + k0 + c4];
            *(uint2*)&Bs[r * 72 + c4] = make_uint2(
                h2u(__floats2half2_rn(wv.x, wv.y)), h2u(__floats2half2_rn(wv.z, wv.w)));
        }
        __syncthreads();

        #pragma unroll
        for (int kk = 0; kk < 64; kk += 16) {
            unsigned af[4][4], bf[4][2];
            #pragma unroll
            for (int mt = 0; mt < 4; mt++)
                ldmx4(af[mt], AFRAG_ADDR(As, wm * 64 + mt * 16, kk, lane));
            #pragma unroll
            for (int nt2 = 0; nt2 < 2; nt2++) {
                unsigned bq4[4];
                ldmx4(bq4, BFRAG_ADDR(Bs, wn * 32 + nt2 * 16, kk, lane));
                bf[nt2 * 2 + 0][0] = bq4[0]; bf[nt2 * 2 + 0][1] = bq4[1];
                bf[nt2 * 2 + 1][0] = bq4[2]; bf[nt2 * 2 + 1][1] = bq4[3];
            }
            #pragma unroll
            for (int mt = 0; mt < 4; mt++)
                #pragma unroll
                for (int nt = 0; nt < 4; nt++)
                    mma_f16(acc[mt][nt], af[mt], bf[nt]);
        }
        __syncthreads();
    }

    #pragma unroll
    for (int nt = 0; nt < 4; nt++) {
        const int col = n0 + wn * 32 + nt * 8 + 2 * tig;
        const float b0v = bias[col], b1v = bias[col + 1];
        #pragma unroll
        for (int mt = 0; mt < 4; mt++) {
            #pragma unroll
            for (int half = 0; half < 2; half++) {
                int m = m0 + wm * 64 + mt * 16 + g + half * 8;
                int b = m >> 11, s = m & (SS - 1);
                int h = col >> 6, hd = col & (HD - 1);
                __half2 hv = __floats2half2_rn(acc[mt][nt][half * 2 + 0] + b0v,
                                               acc[mt][nt][half * 2 + 1] + b1v);
                *(unsigned*)&out[(((size_t)(b * HH + h)) * SS + s) * HD + hd] = h2u(hv);
            }
        }
    }
}

// ---------------------------------------------------------------------------
// Output projection: fp16 in (g_x) -> fp32 out. Same tiling.
// ---------------------------------------------------------------------------
__global__ __launch_bounds__(256) void out_proj(
    const __half* __restrict__ X, const float* __restrict__ W,
    const float* __restrict__ bias, float* __restrict__ out)
{
    const int m0 = blockIdx.y * 128, n0 = blockIdx.x * 128;

    __shared__ __align__(16) __half As[128 * 72];
    __shared__ __align__(16) __half Bs[128 * 72];

    const int t = threadIdx.x;
    const int warp = t >> 5, lane = t & 31;
    const int wm = warp >> 2, wn = warp & 3;
    const int g = lane >> 2, tig = lane & 3;

    float acc[4][4][4] = {};

    for (int k0 = 0; k0 < DD; k0 += 64) {
        #pragma unroll
        for (int i = 0; i < 4; i++) {       // A: 128 rows x 8 chunks of 8 halfs
            int id = i * 256 + t;
            int r = id >> 3, c8 = (id & 7) * 8;
            *(uint4*)&As[r * 72 + c8] = *(const uint4*)&X[(size_t)(m0 + r) * DD + k0 + c8];
        }
        #pragma unroll
        for (int i = 0; i < 8; i++) {       // B: cvt fp32 W
            int id = i * 256 + t;
            int r = id >> 4, c4 = (id & 15) * 4;
            float4 wv = *(const float4*)&W[(size_t)(n0 + r) * DD + k0 + c4];
            *(uint2*)&Bs[r * 72 + c4] = make_uint2(
                h2u(__floats2half2_rn(wv.x, wv.y)), h2u(__floats2half2_rn(wv.z, wv.w)));
        }
        __syncthreads();

        #pragma unroll
        for (int kk = 0; kk < 64; kk += 16) {
            unsigned af[4][4], bf[4][2];
            #pragma unroll
            for (int mt = 0; mt < 4; mt++)
                ldmx4(af[mt], AFRAG_ADDR(As, wm * 64 + mt * 16, kk, lane));
            #pragma unroll
            for (int nt2 = 0; nt2 < 2; nt2++) {
                unsigned bq4[4];
                ldmx4(bq4, BFRAG_ADDR(Bs, wn * 32 + nt2 * 16, kk, lane));
                bf[nt2 * 2 + 0][0] = bq4[0]; bf[nt2 * 2 + 0][1] = bq4[1];
                bf[nt2 * 2 + 1][0] = bq4[2]; bf[nt2 * 2 + 1][1] = bq4[3];
            }
            #pragma unroll
            for (int mt = 0; mt < 4; mt++)
                #pragma unroll
                for (int nt = 0; nt < 4; nt++)
                    mma_f16(acc[mt][nt], af[mt], bf[nt]);
        }
        __syncthreads();
    }

    #pragma unroll
    for (int nt = 0; nt < 4; nt++) {
        const int col = n0 + wn * 32 + nt * 8 + 2 * tig;
        const float b0v = bias[col], b1v = bias[col + 1];
        #pragma unroll
        for (int mt = 0; mt < 4; mt++) {
            #pragma unroll
            for (int half = 0; half < 2; half++) {
                int m = m0 + wm * 64 + mt * 16 + g + half * 8;
                float2 v;
                v.x = acc[mt][nt][half * 2 + 0] + b0v;
                v.y = acc[mt][nt][half * 2 + 1] + b1v;
                *(float2*)&out[(size_t)m * DD + col] = v;
            }
        }
    }
}

// ---------------------------------------------------------------------------
// Fused attention: fp16 storage + cp.async double-buffered pipelines.
// smem (halfs): Qs | Ka Kb | Va Vb | Pa Pb | rowsum(64 f32)
// ---------------------------------------------------------------------------
#define HQS 0
#define HKA 4608
#define HKB 9216
#define HVA 13824
#define HVB 18432
#define HPA 23040
#define HPB 27648
#define HRS 32256
#define ATTN_SMEM_B ((32256 + 128) * 2)   // 64,768 B

// copy one 64x64 half tile (src row stride HD) into smem (stride 72), async
__device__ __forceinline__ void issue_tile(__half* dst, const __half* src, int t)
{
    #pragma unroll
    for (int i = 0; i < 2; i++) {
        int id = i * 256 + t;
        int r = id >> 3, c8 = (id & 7) * 8;
        cp16(dst + r * 72 + c8, src + (size_t)r * HD + c8);
    }
}
// copy one 64x64 half tile from g_p (row stride SS)
__device__ __forceinline__ void issue_ptile(__half* dst, const __half* src, int t)
{
    #pragma unroll
    for (int i = 0; i < 2; i++) {
        int id = i * 256 + t;
        int r = id >> 3, c8 = (id & 7) * 8;
        cp16(dst + r * 72 + c8, src + (size_t)r * SS + c8);
    }
}

__global__ __launch_bounds__(256, 3) void attn_fused(float* __restrict__ dist)
{
    extern __shared__ __half hsm[];
    __half* Qs = hsm + HQS;
    float* rowsum = (float*)(hsm + HRS);

    const int t = threadIdx.x;
    const int warp = t >> 5, lane = t & 31;
    const int wm = warp >> 2, wn = warp & 3;   // 2m x 4n, warp tile 32x16
    const int g = lane >> 2, tig = lane & 3;
    const int bh = blockIdx.y, b = bh >> 3, h = bh & 7;
    const int m0 = blockIdx.x * 64;

    const __half* q = g_q + (size_t)bh * SS * HD;
    const __half* k = g_k + (size_t)bh * SS * HD;
    const __half* v = g_v + (size_t)bh * SS * HD;

    // prologue: K(0) async; Q direct copy; rowsum init
    issue_tile(hsm + HKA, k, t); CP_COMMIT();
    #pragma unroll
    for (int i = 0; i < 2; i++) {
        int id = i * 256 + t;
        int r = id >> 3, c8 = (id & 7) * 8;
        *(uint4*)&Qs[r * 72 + c8] = *(const uint4*)&q[(size_t)(m0 + r) * HD + c8];
    }
    if (t < 64) rowsum[t] = 0.0f;

    float rs[2][2] = {};
    const int pr = t >> 2, pc = (t & 3) * 16;

    // ======== Phase A: S MMA + exp + rowsums + stage P to g_p ========
    for (int it = 0; it < 32; it++) {
        const int n0 = it * 64;
        CP_WAIT0();
        __syncthreads();            // K(it) visible; prev epilogue/g_p done
        if (it < 31) { issue_tile(hsm + ((it & 1) ? HKA : HKB), k + (size_t)(n0 + 64) * HD, t); CP_COMMIT(); }
        const __half* Kc = hsm + ((it & 1) ? HKB : HKA);
        __half* Ps = hsm + HPA;

        float acc[2][2][4] = {};
        #pragma unroll
        for (int kk = 0; kk < 64; kk += 16) {
            unsigned af[2][4], bf[2][2];
            #pragma unroll
            for (int mt = 0; mt < 2; mt++)
                ldmx4(af[mt], AFRAG_ADDR(Qs, wm * 32 + mt * 16, kk, lane));
            {
                unsigned bq2[4];
                ldmx4(bq2, BFRAG_ADDR(Kc, wn * 16, kk, lane));
                bf[0][0] = bq2[0]; bf[0][1] = bq2[1];
                bf[1][0] = bq2[2]; bf[1][1] = bq2[3];
            }
            #pragma unroll
            for (int mt = 0; mt < 2; mt++)
                #pragma unroll
                for (int nt = 0; nt < 2; nt++)
                    mma_f16(acc[mt][nt], af[mt], bf[nt]);
        }

        #pragma unroll
        for (int mt = 0; mt < 2; mt++) {
            #pragma unroll
            for (int half = 0; half < 2; half++) {
                int rowl = wm * 32 + mt * 16 + g + half * 8;
                int row = m0 + rowl;
                unsigned mb = g_mbits[((size_t)b * SS + row) * (SS/32) + (n0 >> 5) + (wn >> 1)];
                int bitbase = (wn & 1) * 16;
                #pragma unroll
                for (int nt = 0; nt < 2; nt++) {
                    int nloc = nt * 8 + 2 * tig;
                    float e0 = ((mb >> (bitbase + nloc)) & 1u) ? 0.0f : ex2f(acc[mt][nt][half*2+0] * CEXP);
                    float e1 = ((mb >> (bitbase + nloc + 1)) & 1u) ? 0.0f : ex2f(acc[mt][nt][half*2+1] * CEXP);
                    rs[mt][half] += e0 + e1;
                    *(unsigned*)&Ps[rowl * 72 + wn * 16 + nloc] = h2u(__floats2half2_rn(e0, e1));
                }
            }
        }
        __syncthreads();

        // coalesced Ps -> g_p: 16 halfs per thread
        {
            uint4 p0 = *(uint4*)&Ps[pr * 72 + pc];
            uint4 p1 = *(uint4*)&Ps[pr * 72 + pc + 8];
            __half* gp = &g_p[((size_t)bh * SS + m0 + pr) * SS + n0 + pc];
            *(uint4*)gp = p0;
            *(uint4*)(gp + 8) = p1;
        }
    }

    // reduce row sums; prologue Phase B copies (overlap with reduction)
    issue_tile(hsm + HVA, v, t);
    issue_ptile(hsm + HPA, &g_p[((size_t)bh * SS + m0) * SS], t);
    CP_COMMIT();
    #pragma unroll
    for (int mt = 0; mt < 2; mt++)
        #pragma unroll
        for (int half = 0; half < 2; half++) {
            float s = rs[mt][half];
            s += __shfl_xor_sync(0xffffffffu, s, 1);
            s += __shfl_xor_sync(0xffffffffu, s, 2);
            if (tig == 0)
                atomicAdd(&rowsum[wm * 32 + mt * 16 + g + half * 8], s);
        }
    __syncthreads();
    if (t < 64) rowsum[t] = 1.0f / rowsum[t];

    // ======== Phase B: normalize->dist + PV MMA ========
    float y[2][2][4] = {};
    const size_t dbase = (size_t)bh * SS * SS;

    for (int it = 0; it < 32; it++) {
        const int n0 = it * 64;
        CP_WAIT0();
        __syncthreads();            // V(it)/P(it) visible; rowsum inv on it==0
        if (it < 31) {
            issue_tile(hsm + ((it & 1) ? HVA : HVB), v + (size_t)(n0 + 64) * HD, t);
            issue_ptile(hsm + ((it & 1) ? HPA : HPB), &g_p[((size_t)bh * SS + m0) * SS + n0 + 64], t);
            CP_COMMIT();
        }
        const __half* Vc = hsm + ((it & 1) ? HVB : HVA);
        const __half* Pc = hsm + ((it & 1) ? HPB : HPA);

        // normalized dist write (float4 coalesced), 16 halfs/thread from Pc
        {
            uint4 p0 = *(const uint4*)&Pc[pr * 72 + pc];
            uint4 p1 = *(const uint4*)&Pc[pr * 72 + pc + 8];
            float inv = rowsum[pr];
            float* dp = &dist[dbase + (size_t)(m0 + pr) * SS + n0 + pc];
            const __half* h0 = (const __half*)&p0;
            const __half* h1 = (const __half*)&p1;
            #pragma unroll
            for (int j = 0; j < 2; j++) {
                float4 o;
                o.x = __half2float(h0[j * 4 + 0]) * inv;
                o.y = __half2float(h0[j * 4 + 1]) * inv;
                o.z = __half2float(h0[j * 4 + 2]) * inv;
                o.w = __half2float(h0[j * 4 + 3]) * inv;
                *(float4*)(dp + j * 4) = o;
            }
            #pragma unroll
            for (int j = 0; j < 2; j++) {
                float4 o;
                o.x = __half2float(h1[j * 4 + 0]) * inv;
                o.y = __half2float(h1[j * 4 + 1]) * inv;
                o.z = __half2float(h1[j * 4 + 2]) * inv;
                o.w = __half2float(h1[j * 4 + 3]) * inv;
                *(float4*)(dp + 8 + j * 4) = o;
            }
        }

        // PV: y += P(unnorm)[64x64] @ V[64x64]
        #pragma unroll
        for (int kk = 0; kk < 64; kk += 16) {
            unsigned af[2][4], bv[4];
            #pragma unroll
            for (int mt = 0; mt < 2; mt++)
                ldmx4(af[mt], AFRAG_ADDR(Pc, wm * 32 + mt * 16, kk, lane));
            ldmx4t(bv, &Vc[(kk + (lane & 15)) * 72 + wn * 16 + (lane >> 4) * 8]);
            #pragma unroll
            for (int mt = 0; mt < 2; mt++) {
                mma_f16(y[mt][0], af[mt], bv + 0);
                mma_f16(y[mt][1], af[mt], bv + 2);
            }
        }
    }

    // write x = y * inv, fp16
    #pragma unroll
    for (int mt = 0; mt < 2; mt++) {
        #pragma unroll
        for (int nt = 0; nt < 2; nt++) {
            #pragma unroll
            for (int half = 0; half < 2; half++) {
                int rowl = wm * 32 + mt * 16 + g + half * 8;
                int row = m0 + rowl;
                int col = wn * 16 + nt * 8 + 2 * tig;
                float inv = rowsum[rowl];
                __half2 hv = __floats2half2_rn(y[mt][nt][half * 2 + 0] * inv,
                                               y[mt][nt][half * 2 + 1] * inv);
                *(unsigned*)&g_x[((size_t)(b * SS + row)) * DD + h * HD + col] = h2u(hv);
            }
        }
    }
}

// ---------------------------------------------------------------------------
extern "C" void kernel_launch(void* const* d_in, const int* in_sizes, int n_in,
                              void* d_out, int out_size)
{
    const float* Q  = (const float*)d_in[0];
    const float* K  = (const float*)d_in[1];
    const float* V  = (const float*)d_in[2];
    const int*   mask = (const int*)d_in[3];
    const float* Wq = (const float*)d_in[4];
    const float* bq = (const float*)d_in[5];
    const float* Wk = (const float*)d_in[6];
    const float* bk = (const float*)d_in[7];
    const float* Wv = (const float*)d_in[8];
    const float* bv = (const float*)d_in[9];
    const float* Wo = (const float*)d_in[10];
    const float* bo = (const float*)d_in[11];

    float* out_x    = (float*)d_out;
    float* out_dist = (float*)d_out + (size_t)BB * SS * DD;

    void* pq; void* pk; void* pv; void* px; void* pbits;
    cudaGetSymbolAddress(&pq, g_q);
    cudaGetSymbolAddress(&pk, g_k);
    cudaGetSymbolAddress(&pv, g_v);
    cudaGetSymbolAddress(&px, g_x);
    cudaGetSymbolAddress(&pbits, g_mbits);

    cudaFuncSetAttribute(attn_fused, cudaFuncAttributeMaxDynamicSharedMemorySize, ATTN_SMEM_B);

    pack_mask_kernel<<<(BB * SS * (SS/32)) / 256, 256>>>(mask, (unsigned*)pbits);

    dim3 gqkv(DD / 128, (BB * SS) / 128, 3);                // (4, 64, 3)
    qkv_proj<<<gqkv, 256>>>(Q, K, V, Wq, bq, Wk, bk, Wv, bv,
                            (__half*)pq, (__half*)pk, (__half*)pv);

    dim3 gattn(SS / 64, BH);                                // (32, 32)
    attn_fused<<<gattn, 256, ATTN_SMEM_B>>>(out_dist);

    dim3 gproj(DD / 128, (BB * SS) / 128);                  // (4, 64)
    out_proj<<<gproj, 256>>>((const __half*)px, Wo, bo, out_x);
}